// round 11
// baseline (speedup 1.0000x reference)
#include <cuda_runtime.h>
#include <math.h>

#define BB    64
#define SS    128
#define DENC  1024
#define HID   512
#define EMB   512
#define VOC   32000
#define TSTEPS 31
#define MASKV -10000000000.0f
#define NLOG  (VOC / 128)     // 250 logits blocks
#define NG    64              // gates-h blocks each (16 n-tiles x 4 k-splits)
#define NATT  (BB * 2)        // 2 attn blocks per batch row

// ------------------- static scratch -------------------
__device__ __align__(256) float g_h[2][BB][HID];
__device__ __align__(256) float g_c[2][BB][HID];
__device__ __align__(256) float g_ctx[BB][DENC];
__device__ __align__(256) float g_gates0[BB][4 * HID];
__device__ __align__(256) float g_gates1[2][BB][4 * HID];       // double-buffered
__device__ __align__(256) unsigned long long g_amax2[2][BB];    // double-buffered
__device__ __align__(256) float g_wcomb[HID][DENC];             // Wcomb[j][d]
__device__ __align__(256) float g_bcomb[DENC];                  // bq @ wk
__device__ __align__(256) float g_k2[BB][SS][HID];              // K2[b,s,j] = enc[b,s]·Wcomb[j]
__device__ __align__(256) float g_sb[BB][SS];                   // bcomb·enc[b,s]
__device__ __align__(256) float g_logits[(size_t)TSTEPS * BB * VOC];   // (t,b,v)

// ------------------- helpers -------------------
__device__ __forceinline__ void fma2(float2& c, float2 a, float2 b) {
    union { float2 f; unsigned long long u; } uc, ua, ub;
    uc.f = c; ua.f = a; ub.f = b;
    asm("fma.rn.f32x2 %0, %1, %2, %0;" : "+l"(uc.u) : "l"(ua.u), "l"(ub.u));
    c = uc.f;
}
__device__ __forceinline__ unsigned fkey(float f) {
    unsigned u = __float_as_uint(f);
    return (u & 0x80000000u) ? ~u : (u | 0x80000000u);
}
__device__ __forceinline__ float sig_(float x) { return 1.0f / (1.0f + expf(-x)); }

// ------------------- staging helpers (32-k chunks, 256 threads) -------------------
__device__ __forceinline__ void stage_A32(float (*As)[68], const float* A, int lda, int kl) {
    int tid = threadIdx.x;
    int m = tid >> 2;
    int kq = (tid & 3) * 8;
    const float4* src = (const float4*)(A + (size_t)m * lda + kl + kq);
    #pragma unroll
    for (int i = 0; i < 2; i++) {
        float4 v = src[i];
        As[kq + i * 4 + 0][m] = v.x; As[kq + i * 4 + 1][m] = v.y;
        As[kq + i * 4 + 2][m] = v.z; As[kq + i * 4 + 3][m] = v.w;
    }
}
__device__ __forceinline__ void stage_W32(float (*Ws)[132], const float* W, int wld,
                                          int n0, int kl) {
    int tid = threadIdx.x;
    int nn = tid >> 1;
    int kq2 = (tid & 1) * 16;
    const float4* src = (const float4*)(W + (size_t)(n0 + nn) * wld + kl + kq2);
    #pragma unroll
    for (int i = 0; i < 4; i++) {
        float4 v = src[i];
        Ws[kq2 + i * 4 + 0][nn] = v.x; Ws[kq2 + i * 4 + 1][nn] = v.y;
        Ws[kq2 + i * 4 + 2][nn] = v.z; Ws[kq2 + i * 4 + 3][nn] = v.w;
    }
}

// ------------------- generic 64xN GEMM body (W n-major), 256 threads -------------------
__device__ __forceinline__ void dev_gemm_body(
    float (*As)[68], float (*Ws)[132],
    const float* __restrict__ A, int lda,
    const float* __restrict__ W, int wld,
    int n0, int kstart, int nchunks32,
    float* __restrict__ C, int ldc, int doStore)
{
    int tid = threadIdx.x;
    int tx = tid & 31, ty = tid >> 5;
    float2 acc[8][2];
    #pragma unroll
    for (int p = 0; p < 8; p++) { acc[p][0] = make_float2(0.f, 0.f); acc[p][1] = make_float2(0.f, 0.f); }

    for (int ci = 0; ci < nchunks32; ci++) {
        int kl = kstart + ci * 32;
        stage_A32(As, A, lda, kl);
        stage_W32(Ws, W, wld, n0, kl);
        __syncthreads();
        #pragma unroll
        for (int kk = 0; kk < 32; kk++) {
            float4 w4 = *(float4*)&Ws[kk][tx * 4];
            float2 wA = make_float2(w4.x, w4.y);
            float2 wB = make_float2(w4.z, w4.w);
            float4 a0 = *(float4*)&As[kk][ty * 8];
            float4 a1 = *(float4*)&As[kk][ty * 8 + 4];
            float av[8] = {a0.x, a0.y, a0.z, a0.w, a1.x, a1.y, a1.z, a1.w};
            #pragma unroll
            for (int p = 0; p < 8; p++) {
                float2 aa = make_float2(av[p], av[p]);
                fma2(acc[p][0], aa, wA);
                fma2(acc[p][1], aa, wB);
            }
        }
        __syncthreads();
    }
    #pragma unroll
    for (int p = 0; p < 8; p++) {
        int m = ty * 8 + p;
        float* cp = C + (size_t)m * ldc + n0 + tx * 4;
        if (doStore) {
            *(float4*)cp = make_float4(acc[p][0].x, acc[p][0].y, acc[p][1].x, acc[p][1].y);
        } else {
            atomicAdd(cp + 0, acc[p][0].x);
            atomicAdd(cp + 1, acc[p][0].y);
            atomicAdd(cp + 2, acc[p][1].x);
            atomicAdd(cp + 3, acc[p][1].y);
        }
    }
}

// ------------------- logits body (K=512, bias + fused argmax), FFMA2 -------------------
__device__ __forceinline__ void dev_logits(
    float (*As)[68], float (*Ws)[132], int n0,
    const float* __restrict__ W, const float* __restrict__ bias,
    float* __restrict__ C, unsigned long long* __restrict__ amaxp)
{
    int tid = threadIdx.x;
    int tx = tid & 31, ty = tid >> 5;
    float2 acc[8][2];
    #pragma unroll
    for (int p = 0; p < 8; p++) { acc[p][0] = make_float2(0.f, 0.f); acc[p][1] = make_float2(0.f, 0.f); }

    const float* A = &g_h[1][0][0];
    for (int kl = 0; kl < HID; kl += 32) {
        stage_A32(As, A, HID, kl);
        stage_W32(Ws, W, HID, n0, kl);
        __syncthreads();
        #pragma unroll
        for (int kk = 0; kk < 32; kk++) {
            float4 w4 = *(float4*)&Ws[kk][tx * 4];
            float2 wA = make_float2(w4.x, w4.y);
            float2 wB = make_float2(w4.z, w4.w);
            float4 a0 = *(float4*)&As[kk][ty * 8];
            float4 a1 = *(float4*)&As[kk][ty * 8 + 4];
            float av[8] = {a0.x, a0.y, a0.z, a0.w, a1.x, a1.y, a1.z, a1.w};
            #pragma unroll
            for (int p = 0; p < 8; p++) {
                float2 aa = make_float2(av[p], av[p]);
                fma2(acc[p][0], aa, wA);
                fma2(acc[p][1], aa, wB);
            }
        }
        __syncthreads();
    }
    int n = n0 + tx * 4;
    float4 bv = *(const float4*)&bias[n];
    #pragma unroll
    for (int p = 0; p < 8; p++) {
        int m = ty * 8 + p;
        float4 v;
        v.x = acc[p][0].x + bv.x;
        v.y = acc[p][0].y + bv.y;
        v.z = acc[p][1].x + bv.z;
        v.w = acc[p][1].y + bv.w;
        *(float4*)(C + (size_t)m * VOC + n) = v;
        unsigned long long key = ((unsigned long long)fkey(v.x) << 32) | (unsigned)(~(n + 0));
        unsigned long long k2  = ((unsigned long long)fkey(v.y) << 32) | (unsigned)(~(n + 1));
        if (k2 > key) key = k2;
        k2 = ((unsigned long long)fkey(v.z) << 32) | (unsigned)(~(n + 2));
        if (k2 > key) key = k2;
        k2 = ((unsigned long long)fkey(v.w) << 32) | (unsigned)(~(n + 3));
        if (k2 > key) key = k2;
        #pragma unroll
        for (int off = 16; off > 0; off >>= 1) {
            unsigned long long o = __shfl_xor_sync(0xffffffffu, key, off);
            if (o > key) key = o;
        }
        if (tx == 0) atomicMax(&amaxp[m], key);
    }
}

// ------------------- attention body: scores from K2, softmax, ctx (d-half per block)
__device__ void dev_attn(float (*As)[68], int b, int dh,
                         const float* __restrict__ enc, const int* __restrict__ mask)
{
    float* sh1 = &As[0][0];          // 512
    float* sal = sh1 + 512;          // 128
    float* red = sal + SS;           // 4
    int tid = threadIdx.x, lane = tid & 31, warp = tid >> 5;

    *(float2*)&sh1[tid * 2] = *(const float2*)&g_h[1][b][tid * 2];
    __syncthreads();

    // scores: 8 warps x 16 s-rows each, dot over K2 (K=512)
    #pragma unroll 1
    for (int i = 0; i < 16; i++) {
        int s = warp * 16 + i;
        const float* kp = &g_k2[b][s][0];
        float acc = 0.f;
        #pragma unroll
        for (int d = lane * 4; d < HID; d += 128) {
            float4 kv = *(const float4*)&kp[d];
            float4 qv = *(const float4*)&sh1[d];
            acc += kv.x * qv.x + kv.y * qv.y + kv.z * qv.z + kv.w * qv.w;
        }
        #pragma unroll
        for (int off = 16; off > 0; off >>= 1) acc += __shfl_down_sync(0xffffffffu, acc, off);
        if (lane == 0) sal[s] = mask[b * SS + s] ? MASKV : (acc + g_sb[b][s]) * (1.0f / 32.0f);
    }
    __syncthreads();
    float v = (tid < SS) ? sal[tid] : MASKV;
    float m = v;
    #pragma unroll
    for (int off = 16; off > 0; off >>= 1) m = fmaxf(m, __shfl_xor_sync(0xffffffffu, m, off));
    if (lane == 0 && warp < 4) red[warp] = m;
    __syncthreads();
    float bm = fmaxf(fmaxf(red[0], red[1]), fmaxf(red[2], red[3]));
    float e = (tid < SS) ? expf(v - bm) : 0.f;
    float sm_ = e;
    #pragma unroll
    for (int off = 16; off > 0; off >>= 1) sm_ += __shfl_xor_sync(0xffffffffu, sm_, off);
    __syncthreads();
    if (lane == 0 && warp < 4) red[warp] = sm_;
    __syncthreads();
    float tot = red[0] + red[1] + red[2] + red[3];
    if (tid < SS) sal[tid] = e / tot;
    __syncthreads();
    // ctx: this block covers d-half dh; 2 cols per thread
    {
        int d = dh * 512 + tid * 2;
        float2 acc = make_float2(0.f, 0.f);
        const float* e2 = enc + (size_t)b * SS * DENC + d;
        #pragma unroll 4
        for (int s = 0; s < SS; s++) {
            float a = sal[s];
            float2 ev = *(const float2*)(e2 + (size_t)s * DENC);
            acc.x += a * ev.x; acc.y += a * ev.y;
        }
        *(float2*)&g_ctx[b][d] = acc;
    }
}

// ------------------- union: logits(t-1) || gates0-h || gates1-h || attn -------------------
__global__ void __launch_bounds__(256) k_union(
    int hasLogits,
    const float* __restrict__ w_out, const float* __restrict__ b_out,
    float* __restrict__ Cl, unsigned long long* __restrict__ amaxW,
    const float* __restrict__ w_hh0, const float* __restrict__ w_hh1,
    float* __restrict__ g1p,
    const float* __restrict__ enc, const int* __restrict__ mask)
{
    __shared__ __align__(16) float As[32][68];
    __shared__ __align__(16) float Ws[32][132];
    int bx = blockIdx.x;
    if (bx < NLOG) {
        if (hasLogits) dev_logits(As, Ws, bx * 128, w_out, b_out, Cl, amaxW);
    } else if (bx < NLOG + NG) {
        int b2 = bx - NLOG;
        dev_gemm_body(As, Ws, &g_h[0][0][0], HID, w_hh0, HID,
                      (b2 & 15) * 128, (b2 >> 4) * 128, 4, &g_gates0[0][0], 4 * HID, 0);
    } else if (bx < NLOG + 2 * NG) {
        int b2 = bx - NLOG - NG;
        dev_gemm_body(As, Ws, &g_h[1][0][0], HID, w_hh1, HID,
                      (b2 & 15) * 128, (b2 >> 4) * 128, 4, g1p, 4 * HID, 0);
    } else {
        int a = bx - (NLOG + 2 * NG);
        dev_attn(As, a >> 1, a & 1, enc, mask);
    }
}

// ------------------- gates0 x-part: [emb(pred) | ctx] @ w_ih0.T -------------------
__global__ void __launch_bounds__(256) k_gx0(
    const float* __restrict__ emb_table, const float* __restrict__ w_ih0,
    const unsigned long long* __restrict__ amaxp)
{
    __shared__ __align__(16) float As[32][68];
    __shared__ __align__(16) float Ws[32][132];
    int tid = threadIdx.x;
    int tx = tid & 31, ty = tid >> 5;
    int n0 = blockIdx.x * 128;
    float2 acc[8][2];
    #pragma unroll
    for (int p = 0; p < 8; p++) { acc[p][0] = make_float2(0.f, 0.f); acc[p][1] = make_float2(0.f, 0.f); }

    int m = tid >> 2;
    int kq = (tid & 3) * 8;
    unsigned pred = ~(unsigned)(amaxp[m] & 0xFFFFFFFFull);

    #pragma unroll
    for (int chunk = 0; chunk < 4; chunk++) {
        int k0 = blockIdx.y * 128 + chunk * 32;
        const float* asrc = (k0 < EMB) ? emb_table + (size_t)pred * EMB + k0 + kq
                                       : &g_ctx[m][k0 - EMB + kq];
        {
            const float4* src = (const float4*)asrc;
            #pragma unroll
            for (int i = 0; i < 2; i++) {
                float4 v = src[i];
                As[kq + i * 4 + 0][m] = v.x; As[kq + i * 4 + 1][m] = v.y;
                As[kq + i * 4 + 2][m] = v.z; As[kq + i * 4 + 3][m] = v.w;
            }
        }
        stage_W32(Ws, w_ih0, EMB + DENC, n0, k0);
        __syncthreads();
        #pragma unroll
        for (int kk = 0; kk < 32; kk++) {
            float4 w4 = *(float4*)&Ws[kk][tx * 4];
            float2 wA = make_float2(w4.x, w4.y);
            float2 wB = make_float2(w4.z, w4.w);
            float4 a0 = *(float4*)&As[kk][ty * 8];
            float4 a1 = *(float4*)&As[kk][ty * 8 + 4];
            float av[8] = {a0.x, a0.y, a0.z, a0.w, a1.x, a1.y, a1.z, a1.w};
            #pragma unroll
            for (int p = 0; p < 8; p++) {
                float2 aa = make_float2(av[p], av[p]);
                fma2(acc[p][0], aa, wA);
                fma2(acc[p][1], aa, wB);
            }
        }
        __syncthreads();
    }
    #pragma unroll
    for (int p = 0; p < 8; p++) {
        int mm = ty * 8 + p;
        float* cp = &g_gates0[mm][n0 + tx * 4];
        atomicAdd(cp + 0, acc[p][0].x);
        atomicAdd(cp + 1, acc[p][0].y);
        atomicAdd(cp + 2, acc[p][1].x);
        atomicAdd(cp + 3, acc[p][1].y);
    }
}

// ------------------- gates1 x-part: h0_new @ w_ih1.T (8 k-splits) -------------------
__global__ void __launch_bounds__(256) k_g1x(const float* __restrict__ w_ih1,
                                             float* __restrict__ g1p)
{
    __shared__ __align__(16) float As[32][68];
    __shared__ __align__(16) float Ws[32][132];
    dev_gemm_body(As, Ws, &g_h[0][0][0], HID, w_ih1, HID,
                  blockIdx.x * 128, blockIdx.y * 64, 2, g1p, 4 * HID, 0);
}

// ------------------- one-time precomputes -------------------
__global__ void __launch_bounds__(256) k_wcomb(const float* __restrict__ wq,
                                               const float* __restrict__ wk) {
    __shared__ __align__(16) float Aq[64][68];
    __shared__ __align__(16) float Bk[64][68];
    int tid = threadIdx.x;
    int d0 = blockIdx.x * 64, j0 = blockIdx.y * 64;
    int tx = tid & 15, ty = tid >> 4;
    float2 acc[4][2];
    #pragma unroll
    for (int p = 0; p < 4; p++) { acc[p][0] = make_float2(0.f, 0.f); acc[p][1] = make_float2(0.f, 0.f); }
    int er = tid >> 4, c4 = (tid & 15) * 4;
    for (int e0 = 0; e0 < DENC; e0 += 64) {
        #pragma unroll
        for (int i = 0; i < 4; i++) {
            int e = e0 + er + i * 16;
            *(float4*)&Aq[er + i * 16][c4] = *(const float4*)&wq[(size_t)e * HID + j0 + c4];
            *(float4*)&Bk[er + i * 16][c4] = *(const float4*)&wk[(size_t)e * DENC + d0 + c4];
        }
        __syncthreads();
        #pragma unroll 8
        for (int kk = 0; kk < 64; kk++) {
            float4 a4 = *(float4*)&Aq[kk][ty * 4];
            float4 w4 = *(float4*)&Bk[kk][tx * 4];
            float2 wA = make_float2(w4.x, w4.y), wB = make_float2(w4.z, w4.w);
            float aa[4] = {a4.x, a4.y, a4.z, a4.w};
            #pragma unroll
            for (int p = 0; p < 4; p++) {
                float2 av = make_float2(aa[p], aa[p]);
                fma2(acc[p][0], av, wA);
                fma2(acc[p][1], av, wB);
            }
        }
        __syncthreads();
    }
    #pragma unroll
    for (int p = 0; p < 4; p++) {
        float4 v = make_float4(acc[p][0].x, acc[p][0].y, acc[p][1].x, acc[p][1].y);
        *(float4*)&g_wcomb[j0 + ty * 4 + p][d0 + tx * 4] = v;
    }
}

__global__ void k_bcomb(const float* __restrict__ bq, const float* __restrict__ wk) {
    int d = blockIdx.x * 256 + threadIdx.x;
    float acc = 0.f;
    #pragma unroll 8
    for (int e = 0; e < DENC; e++) acc += bq[e] * wk[(size_t)e * DENC + d];
    g_bcomb[d] = acc;
}

// K2[b, s, j] = sum_d enc[b,s,d] * Wcomb[j,d]  -- grid (4, 128): x=j-tile, y=(b<<1)|s-half
__global__ void __launch_bounds__(256) k_k2(const float* __restrict__ enc) {
    __shared__ __align__(16) float As[32][68];
    __shared__ __align__(16) float Ws[32][132];
    int j0 = blockIdx.x * 128;
    int b = blockIdx.y >> 1, sh = blockIdx.y & 1;
    dev_gemm_body(As, Ws, enc + ((size_t)b * SS + sh * 64) * DENC, DENC,
                  &g_wcomb[0][0], DENC, j0, 0, 32,
                  &g_k2[b][sh * 64][0], HID, 1);
}

__global__ void k_sb(const float* __restrict__ enc) {
    int b = blockIdx.y;
    int s = blockIdx.x * 4 + (threadIdx.x >> 5);
    int lane = threadIdx.x & 31;
    const float* e = enc + ((size_t)b * SS + s) * DENC;
    float acc = 0.f;
    #pragma unroll
    for (int d = lane * 4; d < DENC; d += 128) {
        float4 ev = *(const float4*)&e[d];
        float4 bv = *(const float4*)&g_bcomb[d];
        acc += ev.x * bv.x + ev.y * bv.y + ev.z * bv.z + ev.w * bv.w;
    }
    #pragma unroll
    for (int off = 16; off > 0; off >>= 1) acc += __shfl_down_sync(0xffffffffu, acc, off);
    if (lane == 0) g_sb[b][s] = acc;
}

// ------------------- init -------------------
__global__ void __launch_bounds__(512) k_init(
    const float* __restrict__ b_ih0, const float* __restrict__ b_hh0,
    const float* __restrict__ b_ih1, const float* __restrict__ b_hh1)
{
    int idx = blockIdx.x * 512 + threadIdx.x;   // 32768
    float* h = &g_h[0][0][0];
    float* c = &g_c[0][0][0];
    #pragma unroll
    for (int i = idx; i < 2 * BB * HID; i += 32768) { h[i] = 0.f; c[i] = 0.f; }
    if (idx < BB) {
        g_amax2[1][idx] = (unsigned long long)(unsigned)(~1u);  // pred0 = START = 1
        g_amax2[0][idx] = 0ull;
    }
    int k4 = idx * 4;
    int kb = k4 & (4 * HID - 1);
    float4 a = *(const float4*)&b_ih0[kb];
    float4 c0 = *(const float4*)&b_hh0[kb];
    a.x += c0.x; a.y += c0.y; a.z += c0.z; a.w += c0.w;
    *(float4*)(&g_gates0[0][0] + k4) = a;
    float4 a1 = *(const float4*)&b_ih1[kb];
    float4 c1 = *(const float4*)&b_hh1[kb];
    a1.x += c1.x; a1.y += c1.y; a1.z += c1.z; a1.w += c1.w;
    *(float4*)(&g_gates1[0][0][0] + k4) = a1;
}

// ------------------- LSTM cells -------------------
__global__ void __launch_bounds__(512) k_cell0() {
    int idx = blockIdx.x * 512 + threadIdx.x;
    int b = idx >> 9, j = idx & (HID - 1);
    float i_ = g_gates0[b][j];
    float f_ = g_gates0[b][HID + j];
    float gg = g_gates0[b][2 * HID + j];
    float o_ = g_gates0[b][3 * HID + j];
    float c_new = sig_(f_) * g_c[0][b][j] + sig_(i_) * tanhf(gg);
    g_c[0][b][j] = c_new;
    g_h[0][b][j] = sig_(o_) * tanhf(c_new);
}

__global__ void __launch_bounds__(512) k_cell1(int p,
    const float* __restrict__ b_ih0, const float* __restrict__ b_hh0,
    const float* __restrict__ b_ih1, const float* __restrict__ b_hh1)
{
    int idx = blockIdx.x * 512 + threadIdx.x;
    int b = idx >> 9, j = idx & (HID - 1);
    float i_ = g_gates1[p][b][j];
    float f_ = g_gates1[p][b][HID + j];
    float gg = g_gates1[p][b][2 * HID + j];
    float o_ = g_gates1[p][b][3 * HID + j];
    float c_new = sig_(f_) * g_c[1][b][j] + sig_(i_) * tanhf(gg);
    g_c[1][b][j] = c_new;
    g_h[1][b][j] = sig_(o_) * tanhf(c_new);
    if (idx < BB) g_amax2[p][idx] = 0ull;
    // presets for step t+1
    int k4 = idx * 4;
    int kb = k4 & (4 * HID - 1);
    float4 a = *(const float4*)&b_ih0[kb];
    float4 c0 = *(const float4*)&b_hh0[kb];
    a.x += c0.x; a.y += c0.y; a.z += c0.z; a.w += c0.w;
    *(float4*)(&g_gates0[0][0] + k4) = a;
    float4 a1 = *(const float4*)&b_ih1[kb];
    float4 c1 = *(const float4*)&b_hh1[kb];
    a1.x += c1.x; a1.y += c1.y; a1.z += c1.z; a1.w += c1.w;
    *(float4*)(&g_gates1[1 - p][0][0] + k4) = a1;
}

// ------------------- final transpose (t,b,v) -> (b,v,t) -------------------
__global__ void __launch_bounds__(256) k_tr(float* __restrict__ out) {
    __shared__ float s[256][32];
    int b = blockIdx.y;
    int v0 = blockIdx.x * 256;
    int tid = threadIdx.x;
    #pragma unroll
    for (int t = 0; t < TSTEPS; t++)
        s[tid][t] = g_logits[((size_t)t * BB + b) * VOC + v0 + tid];
    __syncthreads();
    float* ob = out + ((size_t)b * VOC + v0) * TSTEPS;
    for (int i = tid; i < 256 * TSTEPS; i += 256)
        ob[i] = s[i / TSTEPS][i % TSTEPS];
}

// ------------------- launch -------------------
extern "C" void kernel_launch(void* const* d_in, const int* in_sizes, int n_in,
                              void* d_out, int out_size) {
    const float* enc   = (const float*)d_in[0];
    const int*   mask  = (const int*)d_in[1];
    const float* embt  = (const float*)d_in[2];
    const float* wq    = (const float*)d_in[3];
    const float* bq    = (const float*)d_in[4];
    const float* wk    = (const float*)d_in[5];
    const float* w_ih0 = (const float*)d_in[7];
    const float* w_hh0 = (const float*)d_in[8];
    const float* b_ih0 = (const float*)d_in[9];
    const float* b_hh0 = (const float*)d_in[10];
    const float* w_ih1 = (const float*)d_in[11];
    const float* w_hh1 = (const float*)d_in[12];
    const float* b_ih1 = (const float*)d_in[13];
    const float* b_hh1 = (const float*)d_in[14];
    const float* w_out = (const float*)d_in[15];
    const float* b_out = (const float*)d_in[16];
    float* out = (float*)d_out;

    float* glog = nullptr; float* gg1 = nullptr;
    unsigned long long* gam = nullptr;
    cudaGetSymbolAddress((void**)&glog, g_logits);
    cudaGetSymbolAddress((void**)&gg1, g_gates1);
    cudaGetSymbolAddress((void**)&gam, g_amax2);

    k_wcomb<<<dim3(16, 8), 256>>>(wq, wk);
    k_bcomb<<<4, 256>>>(bq, wk);
    k_k2<<<dim3(4, 128), 256>>>(enc);
    k_sb<<<dim3(32, 64), 128>>>(enc);
    k_init<<<64, 512>>>(b_ih0, b_hh0, b_ih1, b_hh1);

    for (int t = 0; t < TSTEPS; t++) {
        int p = t & 1;
        int pm = (t > 0) ? ((t - 1) & 1) : 0;
        k_union<<<NLOG + 2 * NG + NATT, 256>>>(
            t > 0, w_out, b_out,
            glog + (size_t)(t > 0 ? t - 1 : 0) * BB * VOC,
            gam + (size_t)pm * BB,
            w_hh0, w_hh1,
            gg1 + (size_t)p * BB * 4 * HID,
            enc, mask);
        k_gx0<<<dim3(16, 12), 256>>>(embt, w_ih0, gam + (size_t)(1 - p) * BB);
        k_cell0<<<64, 512>>>();
        k_g1x<<<dim3(16, 8), 256>>>(w_ih1, gg1 + (size_t)p * BB * 4 * HID);
        k_cell1<<<64, 512>>>(p, b_ih0, b_hh0, b_ih1, b_hh1);
    }
    // final logits (t = TSTEPS-1): parity of 30 is 0
    k_union<<<NLOG, 256>>>(1, w_out, b_out,
                           glog + (size_t)(TSTEPS - 1) * BB * VOC,
                           gam + 0, w_hh0, w_hh1, gg1, enc, mask);
    k_tr<<<dim3(VOC / 256, BB), 256>>>(out);
}

// round 12
// speedup vs baseline: 1.0611x; 1.0611x over previous
#include <cuda_runtime.h>
#include <math.h>

#define BB    64
#define SS    128
#define DENC  1024
#define HID   512
#define EMB   512
#define VOC   32000
#define TSTEPS 31
#define MASKV -10000000000.0f
#define NLOG  (VOC / 128)     // 250 logits blocks
#define NG    64              // gates-h blocks each (16 n-tiles x 4 k-splits)

// ------------------- static scratch -------------------
__device__ __align__(256) float g_h[2][BB][HID];
__device__ __align__(256) float g_c0[2][BB][HID];               // layer-0 cell, parity buffered
__device__ __align__(256) float g_c1[BB][HID];                  // layer-1 cell
__device__ __align__(256) float g_ctx[BB][DENC];
__device__ __align__(256) float g_gates0[BB][4 * HID];
__device__ __align__(256) float g_gates1[2][BB][4 * HID];       // double-buffered
__device__ __align__(256) unsigned long long g_amax2[2][BB];    // double-buffered
__device__ __align__(256) float g_wcomb[HID][DENC];             // Wcomb[j][d]
__device__ __align__(256) float g_bcomb[DENC];                  // bq @ wk
__device__ __align__(256) float g_logits[(size_t)TSTEPS * BB * VOC];   // (t,b,v)

// ------------------- helpers -------------------
__device__ __forceinline__ void fma2(float2& c, float2 a, float2 b) {
    union { float2 f; unsigned long long u; } uc, ua, ub;
    uc.f = c; ua.f = a; ub.f = b;
    asm("fma.rn.f32x2 %0, %1, %2, %0;" : "+l"(uc.u) : "l"(ua.u), "l"(ub.u));
    c = uc.f;
}
__device__ __forceinline__ unsigned fkey(float f) {
    unsigned u = __float_as_uint(f);
    return (u & 0x80000000u) ? ~u : (u | 0x80000000u);
}
__device__ __forceinline__ float sig_(float x) { return 1.0f / (1.0f + expf(-x)); }

// ------------------- staging helpers (32-k chunks, 256 threads) -------------------
__device__ __forceinline__ void stage_A32(float (*As)[68], const float* A, int lda, int kl) {
    int tid = threadIdx.x;
    int m = tid >> 2;
    int kq = (tid & 3) * 8;
    const float4* src = (const float4*)(A + (size_t)m * lda + kl + kq);
    #pragma unroll
    for (int i = 0; i < 2; i++) {
        float4 v = src[i];
        As[kq + i * 4 + 0][m] = v.x; As[kq + i * 4 + 1][m] = v.y;
        As[kq + i * 4 + 2][m] = v.z; As[kq + i * 4 + 3][m] = v.w;
    }
}
__device__ __forceinline__ void stage_W32(float (*Ws)[132], const float* W, int wld,
                                          int n0, int kl) {
    int tid = threadIdx.x;
    int nn = tid >> 1;
    int kq2 = (tid & 1) * 16;
    const float4* src = (const float4*)(W + (size_t)(n0 + nn) * wld + kl + kq2);
    #pragma unroll
    for (int i = 0; i < 4; i++) {
        float4 v = src[i];
        Ws[kq2 + i * 4 + 0][nn] = v.x; Ws[kq2 + i * 4 + 1][nn] = v.y;
        Ws[kq2 + i * 4 + 2][nn] = v.z; Ws[kq2 + i * 4 + 3][nn] = v.w;
    }
}

// ------------------- generic 64xN GEMM body (W n-major), 256 threads -------------------
__device__ __forceinline__ void dev_gemm_body(
    float (*As)[68], float (*Ws)[132],
    const float* __restrict__ A, int lda,
    const float* __restrict__ W, int wld,
    int n0, int kstart, int nchunks32,
    float* __restrict__ C, int ldc)
{
    int tid = threadIdx.x;
    int tx = tid & 31, ty = tid >> 5;
    float2 acc[8][2];
    #pragma unroll
    for (int p = 0; p < 8; p++) { acc[p][0] = make_float2(0.f, 0.f); acc[p][1] = make_float2(0.f, 0.f); }

    for (int ci = 0; ci < nchunks32; ci++) {
        int kl = kstart + ci * 32;
        stage_A32(As, A, lda, kl);
        stage_W32(Ws, W, wld, n0, kl);
        __syncthreads();
        #pragma unroll
        for (int kk = 0; kk < 32; kk++) {
            float4 w4 = *(float4*)&Ws[kk][tx * 4];
            float2 wA = make_float2(w4.x, w4.y);
            float2 wB = make_float2(w4.z, w4.w);
            float4 a0 = *(float4*)&As[kk][ty * 8];
            float4 a1 = *(float4*)&As[kk][ty * 8 + 4];
            float av[8] = {a0.x, a0.y, a0.z, a0.w, a1.x, a1.y, a1.z, a1.w};
            #pragma unroll
            for (int p = 0; p < 8; p++) {
                float2 aa = make_float2(av[p], av[p]);
                fma2(acc[p][0], aa, wA);
                fma2(acc[p][1], aa, wB);
            }
        }
        __syncthreads();
    }
    #pragma unroll
    for (int p = 0; p < 8; p++) {
        int m = ty * 8 + p;
        float* cp = C + (size_t)m * ldc + n0 + tx * 4;
        atomicAdd(cp + 0, acc[p][0].x);
        atomicAdd(cp + 1, acc[p][0].y);
        atomicAdd(cp + 2, acc[p][1].x);
        atomicAdd(cp + 3, acc[p][1].y);
    }
}

// ------------------- logits body (K=512, bias + fused argmax), FFMA2 -------------------
__device__ __forceinline__ void dev_logits(
    float (*As)[68], float (*Ws)[132], int n0,
    const float* __restrict__ W, const float* __restrict__ bias,
    float* __restrict__ C, unsigned long long* __restrict__ amaxp)
{
    int tid = threadIdx.x;
    int tx = tid & 31, ty = tid >> 5;
    float2 acc[8][2];
    #pragma unroll
    for (int p = 0; p < 8; p++) { acc[p][0] = make_float2(0.f, 0.f); acc[p][1] = make_float2(0.f, 0.f); }

    const float* A = &g_h[1][0][0];
    for (int kl = 0; kl < HID; kl += 32) {
        stage_A32(As, A, HID, kl);
        stage_W32(Ws, W, HID, n0, kl);
        __syncthreads();
        #pragma unroll
        for (int kk = 0; kk < 32; kk++) {
            float4 w4 = *(float4*)&Ws[kk][tx * 4];
            float2 wA = make_float2(w4.x, w4.y);
            float2 wB = make_float2(w4.z, w4.w);
            float4 a0 = *(float4*)&As[kk][ty * 8];
            float4 a1 = *(float4*)&As[kk][ty * 8 + 4];
            float av[8] = {a0.x, a0.y, a0.z, a0.w, a1.x, a1.y, a1.z, a1.w};
            #pragma unroll
            for (int p = 0; p < 8; p++) {
                float2 aa = make_float2(av[p], av[p]);
                fma2(acc[p][0], aa, wA);
                fma2(acc[p][1], aa, wB);
            }
        }
        __syncthreads();
    }
    int n = n0 + tx * 4;
    float4 bv = *(const float4*)&bias[n];
    #pragma unroll
    for (int p = 0; p < 8; p++) {
        int m = ty * 8 + p;
        float4 v;
        v.x = acc[p][0].x + bv.x;
        v.y = acc[p][0].y + bv.y;
        v.z = acc[p][1].x + bv.z;
        v.w = acc[p][1].y + bv.w;
        *(float4*)(C + (size_t)m * VOC + n) = v;
        unsigned long long key = ((unsigned long long)fkey(v.x) << 32) | (unsigned)(~(n + 0));
        unsigned long long k2  = ((unsigned long long)fkey(v.y) << 32) | (unsigned)(~(n + 1));
        if (k2 > key) key = k2;
        k2 = ((unsigned long long)fkey(v.z) << 32) | (unsigned)(~(n + 2));
        if (k2 > key) key = k2;
        k2 = ((unsigned long long)fkey(v.w) << 32) | (unsigned)(~(n + 3));
        if (k2 > key) key = k2;
        #pragma unroll
        for (int off = 16; off > 0; off >>= 1) {
            unsigned long long o = __shfl_xor_sync(0xffffffffu, key, off);
            if (o > key) key = o;
        }
        if (tx == 0) atomicMax(&amaxp[m], key);
    }
}

// ------------------- attention body: inline r = h1@Wcomb + bcomb, scores/softmax/ctx
__device__ void dev_attn(float (*As)[68], float (*Ws)[132], int b,
                         const float* __restrict__ enc, const int* __restrict__ mask)
{
    float* sh1 = &As[0][0];          // 512 (As holds 32*68=2176 floats)
    float* sal = sh1 + 512;          // 128
    float* red = sal + SS;           // 4
    float* sr  = &Ws[0][0];          // 1024 (Ws holds 32*132=4224 floats)
    int tid = threadIdx.x, lane = tid & 31, warp = tid >> 5;

    *(float2*)&sh1[tid * 2] = *(const float2*)&g_h[1][b][tid * 2];
    __syncthreads();

    // r[d] = bcomb[d] + sum_j h1[j] * Wcomb[j][d]; 4 cols per thread
    {
        int d = tid * 4;
        float4 acc = *(const float4*)&g_bcomb[d];
        const float* wc = &g_wcomb[0][d];
        #pragma unroll 8
        for (int j = 0; j < HID; j++) {
            float hj = sh1[j];
            float4 w = *(const float4*)(wc + (size_t)j * DENC);
            acc.x += hj * w.x; acc.y += hj * w.y;
            acc.z += hj * w.z; acc.w += hj * w.w;
        }
        *(float4*)&sr[d] = acc;
    }
    __syncthreads();

    const float* eb = enc + (size_t)b * SS * DENC;
    #pragma unroll 1
    for (int i = 0; i < 16; i++) {
        int s = warp * 16 + i;
        const float* e = eb + (size_t)s * DENC;
        float acc = 0.f;
        #pragma unroll
        for (int d = lane * 4; d < DENC; d += 128) {
            float4 ev = *(const float4*)&e[d];
            float4 qv = *(const float4*)&sr[d];
            acc += ev.x * qv.x + ev.y * qv.y + ev.z * qv.z + ev.w * qv.w;
        }
        #pragma unroll
        for (int off = 16; off > 0; off >>= 1) acc += __shfl_down_sync(0xffffffffu, acc, off);
        if (lane == 0) sal[s] = mask[b * SS + s] ? MASKV : acc * (1.0f / 32.0f);
    }
    __syncthreads();
    float v = (tid < SS) ? sal[tid] : MASKV;
    float m = v;
    #pragma unroll
    for (int off = 16; off > 0; off >>= 1) m = fmaxf(m, __shfl_xor_sync(0xffffffffu, m, off));
    if (lane == 0 && warp < 4) red[warp] = m;
    __syncthreads();
    float bm = fmaxf(fmaxf(red[0], red[1]), fmaxf(red[2], red[3]));
    float e = (tid < SS) ? expf(v - bm) : 0.f;
    float sm_ = e;
    #pragma unroll
    for (int off = 16; off > 0; off >>= 1) sm_ += __shfl_xor_sync(0xffffffffu, sm_, off);
    __syncthreads();
    if (lane == 0 && warp < 4) red[warp] = sm_;
    __syncthreads();
    float tot = red[0] + red[1] + red[2] + red[3];
    if (tid < SS) sal[tid] = e / tot;
    __syncthreads();
    {
        int d = tid * 4;
        float4 acc = make_float4(0.f, 0.f, 0.f, 0.f);
        const float* e2 = eb + d;
        #pragma unroll 4
        for (int s = 0; s < SS; s++) {
            float a = sal[s];
            float4 ev = *(const float4*)(e2 + (size_t)s * DENC);
            acc.x += a * ev.x; acc.y += a * ev.y; acc.z += a * ev.z; acc.w += a * ev.w;
        }
        *(float4*)&g_ctx[b][d] = acc;
    }
}

// ------------------- union: logits(t-1) || gates0-h || gates1-h || attn -------------------
__global__ void __launch_bounds__(256) k_union(
    int hasLogits,
    const float* __restrict__ w_out, const float* __restrict__ b_out,
    float* __restrict__ Cl, unsigned long long* __restrict__ amaxW,
    const float* __restrict__ w_hh0, const float* __restrict__ w_hh1,
    float* __restrict__ g1p,
    const float* __restrict__ enc, const int* __restrict__ mask)
{
    __shared__ __align__(16) float As[32][68];
    __shared__ __align__(16) float Ws[32][132];
    int bx = blockIdx.x;
    if (bx < NLOG) {
        if (hasLogits) dev_logits(As, Ws, bx * 128, w_out, b_out, Cl, amaxW);
    } else if (bx < NLOG + NG) {
        int b2 = bx - NLOG;
        dev_gemm_body(As, Ws, &g_h[0][0][0], HID, w_hh0, HID,
                      (b2 & 15) * 128, (b2 >> 4) * 128, 4, &g_gates0[0][0], 4 * HID);
    } else if (bx < NLOG + 2 * NG) {
        int b2 = bx - NLOG - NG;
        dev_gemm_body(As, Ws, &g_h[1][0][0], HID, w_hh1, HID,
                      (b2 & 15) * 128, (b2 >> 4) * 128, 4, g1p, 4 * HID);
    } else {
        dev_attn(As, Ws, bx - (NLOG + 2 * NG), enc, mask);
    }
}

// ------------------- gates0 x-part: [emb(pred) | ctx] @ w_ih0.T -------------------
__global__ void __launch_bounds__(256) k_gx0(
    const float* __restrict__ emb_table, const float* __restrict__ w_ih0,
    const unsigned long long* __restrict__ amaxp)
{
    __shared__ __align__(16) float As[32][68];
    __shared__ __align__(16) float Ws[32][132];
    int tid = threadIdx.x;
    int tx = tid & 31, ty = tid >> 5;
    int n0 = blockIdx.x * 128;
    float2 acc[8][2];
    #pragma unroll
    for (int p = 0; p < 8; p++) { acc[p][0] = make_float2(0.f, 0.f); acc[p][1] = make_float2(0.f, 0.f); }

    int m = tid >> 2;
    int kq = (tid & 3) * 8;
    unsigned pred = ~(unsigned)(amaxp[m] & 0xFFFFFFFFull);

    #pragma unroll
    for (int chunk = 0; chunk < 4; chunk++) {
        int k0 = blockIdx.y * 128 + chunk * 32;
        const float* asrc = (k0 < EMB) ? emb_table + (size_t)pred * EMB + k0 + kq
                                       : &g_ctx[m][k0 - EMB + kq];
        {
            const float4* src = (const float4*)asrc;
            #pragma unroll
            for (int i = 0; i < 2; i++) {
                float4 v = src[i];
                As[kq + i * 4 + 0][m] = v.x; As[kq + i * 4 + 1][m] = v.y;
                As[kq + i * 4 + 2][m] = v.z; As[kq + i * 4 + 3][m] = v.w;
            }
        }
        stage_W32(Ws, w_ih0, EMB + DENC, n0, k0);
        __syncthreads();
        #pragma unroll
        for (int kk = 0; kk < 32; kk++) {
            float4 w4 = *(float4*)&Ws[kk][tx * 4];
            float2 wA = make_float2(w4.x, w4.y);
            float2 wB = make_float2(w4.z, w4.w);
            float4 a0 = *(float4*)&As[kk][ty * 8];
            float4 a1 = *(float4*)&As[kk][ty * 8 + 4];
            float av[8] = {a0.x, a0.y, a0.z, a0.w, a1.x, a1.y, a1.z, a1.w};
            #pragma unroll
            for (int p = 0; p < 8; p++) {
                float2 aa = make_float2(av[p], av[p]);
                fma2(acc[p][0], aa, wA);
                fma2(acc[p][1], aa, wB);
            }
        }
        __syncthreads();
    }
    #pragma unroll
    for (int p = 0; p < 8; p++) {
        int mm = ty * 8 + p;
        float* cp = &g_gates0[mm][n0 + tx * 4];
        atomicAdd(cp + 0, acc[p][0].x);
        atomicAdd(cp + 1, acc[p][0].y);
        atomicAdd(cp + 2, acc[p][1].x);
        atomicAdd(cp + 3, acc[p][1].y);
    }
}

// ------------------- gates1 x-part with FUSED cell0 prologue -------------------
// block (x = n-tile 0..15, y = k-split 0..7). Prologue: cell0 for units
// j in [y*64, y*64+64) (duplicated across the 16 x-blocks; c0 parity-buffered
// so the RMW is race-free; duplicate writes are identical). Then GEMM reads
// the h0 values this block just wrote (visible after __syncthreads()).
__global__ void __launch_bounds__(256) k_g1x(int rp, const float* __restrict__ w_ih1,
                                             float* __restrict__ g1p)
{
    __shared__ __align__(16) float As[32][68];
    __shared__ __align__(16) float Ws[32][132];
    int y = blockIdx.y;
    int tid = threadIdx.x;
    #pragma unroll
    for (int i = 0; i < 16; i++) {
        int e = tid + i * 256;           // 0..4095
        int b = e >> 6;
        int j = y * 64 + (e & 63);
        float i_ = g_gates0[b][j];
        float f_ = g_gates0[b][HID + j];
        float gg = g_gates0[b][2 * HID + j];
        float o_ = g_gates0[b][3 * HID + j];
        float cn = sig_(f_) * g_c0[rp][b][j] + sig_(i_) * tanhf(gg);
        g_c0[1 - rp][b][j] = cn;
        g_h[0][b][j] = sig_(o_) * tanhf(cn);
    }
    __syncthreads();
    dev_gemm_body(As, Ws, &g_h[0][0][0], HID, w_ih1, HID,
                  blockIdx.x * 128, y * 64, 2, g1p, 4 * HID);
}

// ------------------- one-time precomputes -------------------
__global__ void __launch_bounds__(256) k_wcomb(const float* __restrict__ wq,
                                               const float* __restrict__ wk) {
    __shared__ __align__(16) float Aq[64][68];
    __shared__ __align__(16) float Bk[64][68];
    int tid = threadIdx.x;
    int d0 = blockIdx.x * 64, j0 = blockIdx.y * 64;
    int tx = tid & 15, ty = tid >> 4;
    float2 acc[4][2];
    #pragma unroll
    for (int p = 0; p < 4; p++) { acc[p][0] = make_float2(0.f, 0.f); acc[p][1] = make_float2(0.f, 0.f); }
    int er = tid >> 4, c4 = (tid & 15) * 4;
    for (int e0 = 0; e0 < DENC; e0 += 64) {
        #pragma unroll
        for (int i = 0; i < 4; i++) {
            int e = e0 + er + i * 16;
            *(float4*)&Aq[er + i * 16][c4] = *(const float4*)&wq[(size_t)e * HID + j0 + c4];
            *(float4*)&Bk[er + i * 16][c4] = *(const float4*)&wk[(size_t)e * DENC + d0 + c4];
        }
        __syncthreads();
        #pragma unroll 8
        for (int kk = 0; kk < 64; kk++) {
            float4 a4 = *(float4*)&Aq[kk][ty * 4];
            float4 w4 = *(float4*)&Bk[kk][tx * 4];
            float2 wA = make_float2(w4.x, w4.y), wB = make_float2(w4.z, w4.w);
            float aa[4] = {a4.x, a4.y, a4.z, a4.w};
            #pragma unroll
            for (int p = 0; p < 4; p++) {
                float2 av = make_float2(aa[p], aa[p]);
                fma2(acc[p][0], av, wA);
                fma2(acc[p][1], av, wB);
            }
        }
        __syncthreads();
    }
    #pragma unroll
    for (int p = 0; p < 4; p++) {
        float4 v = make_float4(acc[p][0].x, acc[p][0].y, acc[p][1].x, acc[p][1].y);
        *(float4*)&g_wcomb[j0 + ty * 4 + p][d0 + tx * 4] = v;
    }
}

__global__ void k_bcomb(const float* __restrict__ bq, const float* __restrict__ wk) {
    int d = blockIdx.x * 256 + threadIdx.x;
    float acc = 0.f;
    #pragma unroll 8
    for (int e = 0; e < DENC; e++) acc += bq[e] * wk[(size_t)e * DENC + d];
    g_bcomb[d] = acc;
}

// ------------------- init -------------------
__global__ void __launch_bounds__(512) k_init(
    const float* __restrict__ b_ih0, const float* __restrict__ b_hh0,
    const float* __restrict__ b_ih1, const float* __restrict__ b_hh1)
{
    int idx = blockIdx.x * 512 + threadIdx.x;   // 32768
    float* h = &g_h[0][0][0];
    float* c0 = &g_c0[0][0][0];
    float* c1 = &g_c1[0][0];
    #pragma unroll
    for (int i = idx; i < 2 * BB * HID; i += 32768) { h[i] = 0.f; c0[i] = 0.f; }
    for (int i = idx; i < BB * HID; i += 32768) c1[i] = 0.f;
    if (idx < BB) {
        g_amax2[1][idx] = (unsigned long long)(unsigned)(~1u);  // pred0 = START = 1
        g_amax2[0][idx] = 0ull;
    }
    int k4 = idx * 4;
    int kb = k4 & (4 * HID - 1);
    float4 a = *(const float4*)&b_ih0[kb];
    float4 cc0 = *(const float4*)&b_hh0[kb];
    a.x += cc0.x; a.y += cc0.y; a.z += cc0.z; a.w += cc0.w;
    *(float4*)(&g_gates0[0][0] + k4) = a;
    float4 a1 = *(const float4*)&b_ih1[kb];
    float4 cc1 = *(const float4*)&b_hh1[kb];
    a1.x += cc1.x; a1.y += cc1.y; a1.z += cc1.z; a1.w += cc1.w;
    *(float4*)(&g_gates1[0][0][0] + k4) = a1;
}

// ------------------- LSTM cell 1 -------------------
__global__ void __launch_bounds__(512) k_cell1(int p,
    const float* __restrict__ b_ih0, const float* __restrict__ b_hh0,
    const float* __restrict__ b_ih1, const float* __restrict__ b_hh1)
{
    int idx = blockIdx.x * 512 + threadIdx.x;
    int b = idx >> 9, j = idx & (HID - 1);
    float i_ = g_gates1[p][b][j];
    float f_ = g_gates1[p][b][HID + j];
    float gg = g_gates1[p][b][2 * HID + j];
    float o_ = g_gates1[p][b][3 * HID + j];
    float c_new = sig_(f_) * g_c1[b][j] + sig_(i_) * tanhf(gg);
    g_c1[b][j] = c_new;
    g_h[1][b][j] = sig_(o_) * tanhf(c_new);
    if (idx < BB) g_amax2[p][idx] = 0ull;
    // presets for step t+1
    int k4 = idx * 4;
    int kb = k4 & (4 * HID - 1);
    float4 a = *(const float4*)&b_ih0[kb];
    float4 c0 = *(const float4*)&b_hh0[kb];
    a.x += c0.x; a.y += c0.y; a.z += c0.z; a.w += c0.w;
    *(float4*)(&g_gates0[0][0] + k4) = a;
    float4 a1 = *(const float4*)&b_ih1[kb];
    float4 c1 = *(const float4*)&b_hh1[kb];
    a1.x += c1.x; a1.y += c1.y; a1.z += c1.z; a1.w += c1.w;
    *(float4*)(&g_gates1[1 - p][0][0] + k4) = a1;
}

// ------------------- final transpose (t,b,v) -> (b,v,t) -------------------
__global__ void __launch_bounds__(256) k_tr(float* __restrict__ out) {
    __shared__ float s[256][32];
    int b = blockIdx.y;
    int v0 = blockIdx.x * 256;
    int tid = threadIdx.x;
    #pragma unroll
    for (int t = 0; t < TSTEPS; t++)
        s[tid][t] = g_logits[((size_t)t * BB + b) * VOC + v0 + tid];
    __syncthreads();
    float* ob = out + ((size_t)b * VOC + v0) * TSTEPS;
    for (int i = tid; i < 256 * TSTEPS; i += 256)
        ob[i] = s[i / TSTEPS][i % TSTEPS];
}

// ------------------- launch -------------------
extern "C" void kernel_launch(void* const* d_in, const int* in_sizes, int n_in,
                              void* d_out, int out_size) {
    const float* enc   = (const float*)d_in[0];
    const int*   mask  = (const int*)d_in[1];
    const float* embt  = (const float*)d_in[2];
    const float* wq    = (const float*)d_in[3];
    const float* bq    = (const float*)d_in[4];
    const float* wk    = (const float*)d_in[5];
    const float* w_ih0 = (const float*)d_in[7];
    const float* w_hh0 = (const float*)d_in[8];
    const float* b_ih0 = (const float*)d_in[9];
    const float* b_hh0 = (const float*)d_in[10];
    const float* w_ih1 = (const float*)d_in[11];
    const float* w_hh1 = (const float*)d_in[12];
    const float* b_ih1 = (const float*)d_in[13];
    const float* b_hh1 = (const float*)d_in[14];
    const float* w_out = (const float*)d_in[15];
    const float* b_out = (const float*)d_in[16];
    float* out = (float*)d_out;

    float* glog = nullptr; float* gg1 = nullptr;
    unsigned long long* gam = nullptr;
    cudaGetSymbolAddress((void**)&glog, g_logits);
    cudaGetSymbolAddress((void**)&gg1, g_gates1);
    cudaGetSymbolAddress((void**)&gam, g_amax2);

    k_wcomb<<<dim3(16, 8), 256>>>(wq, wk);
    k_bcomb<<<4, 256>>>(bq, wk);
    k_init<<<64, 512>>>(b_ih0, b_hh0, b_ih1, b_hh1);

    for (int t = 0; t < TSTEPS; t++) {
        int p = t & 1;
        int pm = (t > 0) ? ((t - 1) & 1) : 0;
        k_union<<<NLOG + 2 * NG + BB, 256>>>(
            t > 0, w_out, b_out,
            glog + (size_t)(t > 0 ? t - 1 : 0) * BB * VOC,
            gam + (size_t)pm * BB,
            w_hh0, w_hh1,
            gg1 + (size_t)p * BB * 4 * HID,
            enc, mask);
        k_gx0<<<dim3(16, 12), 256>>>(embt, w_ih0, gam + (size_t)(1 - p) * BB);
        k_g1x<<<dim3(16, 8), 256>>>(p, w_ih1, gg1 + (size_t)p * BB * 4 * HID);
        k_cell1<<<64, 512>>>(p, b_ih0, b_hh0, b_ih1, b_hh1);
    }
    // final logits (t = TSTEPS-1): parity of 30 is 0
    k_union<<<NLOG, 256>>>(1, w_out, b_out,
                           glog + (size_t)(TSTEPS - 1) * BB * VOC,
                           gam + 0, w_hh0, w_hh1, gg1, enc, mask);
    k_tr<<<dim3(VOC / 256, BB), 256>>>(out);
}

// round 13
// speedup vs baseline: 1.1628x; 1.0958x over previous
#include <cuda_runtime.h>
#include <math.h>

#define BB    64
#define SS    128
#define DENC  1024
#define HID   512
#define EMB   512
#define VOC   32000
#define TSTEPS 31
#define MASKV -10000000000.0f
#define NLOG  (VOC / 128)     // 250 logits blocks
#define NG    64              // gates-h blocks each (16 n-tiles x 4 k-splits)

// ------------------- static scratch -------------------
__device__ __align__(256) float g_h[2][BB][HID];
__device__ __align__(256) float g_c[2][BB][HID];
__device__ __align__(256) float g_ctx[BB][DENC];
__device__ __align__(256) float g_gates0[BB][4 * HID];
__device__ __align__(256) float g_gates1[2][BB][4 * HID];       // double-buffered
__device__ __align__(256) unsigned long long g_amax2[2][BB];    // double-buffered
__device__ __align__(256) float g_wcomb[HID][DENC];             // Wcomb[j][d]
__device__ __align__(256) float g_bcomb[DENC];                  // bq @ wk
__device__ __align__(256) float g_logits[(size_t)TSTEPS * BB * VOC];   // (t,b,v)

// ------------------- helpers -------------------
__device__ __forceinline__ void fma2(float2& c, float2 a, float2 b) {
    union { float2 f; unsigned long long u; } uc, ua, ub;
    uc.f = c; ua.f = a; ub.f = b;
    asm("fma.rn.f32x2 %0, %1, %2, %0;" : "+l"(uc.u) : "l"(ua.u), "l"(ub.u));
    c = uc.f;
}
__device__ __forceinline__ unsigned fkey(float f) {
    unsigned u = __float_as_uint(f);
    return (u & 0x80000000u) ? ~u : (u | 0x80000000u);
}
__device__ __forceinline__ float sig_(float x) { return 1.0f / (1.0f + expf(-x)); }

// ------------------- staging helpers (32-k chunks, 256 threads) -------------------
__device__ __forceinline__ void stage_A32(float (*As)[68], const float* A, int lda, int kl) {
    int tid = threadIdx.x;
    int m = tid >> 2;
    int kq = (tid & 3) * 8;
    const float4* src = (const float4*)(A + (size_t)m * lda + kl + kq);
    #pragma unroll
    for (int i = 0; i < 2; i++) {
        float4 v = src[i];
        As[kq + i * 4 + 0][m] = v.x; As[kq + i * 4 + 1][m] = v.y;
        As[kq + i * 4 + 2][m] = v.z; As[kq + i * 4 + 3][m] = v.w;
    }
}
__device__ __forceinline__ void stage_W32(float (*Ws)[132], const float* W, int wld,
                                          int n0, int kl) {
    int tid = threadIdx.x;
    int nn = tid >> 1;
    int kq2 = (tid & 1) * 16;
    const float4* src = (const float4*)(W + (size_t)(n0 + nn) * wld + kl + kq2);
    #pragma unroll
    for (int i = 0; i < 4; i++) {
        float4 v = src[i];
        Ws[kq2 + i * 4 + 0][nn] = v.x; Ws[kq2 + i * 4 + 1][nn] = v.y;
        Ws[kq2 + i * 4 + 2][nn] = v.z; Ws[kq2 + i * 4 + 3][nn] = v.w;
    }
}

// ------------------- generic 64xN GEMM body (W n-major), 256 threads -------------------
__device__ __forceinline__ void dev_gemm_body(
    float (*As)[68], float (*Ws)[132],
    const float* __restrict__ A, int lda,
    const float* __restrict__ W, int wld,
    int n0, int kstart, int nchunks32,
    float* __restrict__ C, int ldc)
{
    int tid = threadIdx.x;
    int tx = tid & 31, ty = tid >> 5;
    float2 acc[8][2];
    #pragma unroll
    for (int p = 0; p < 8; p++) { acc[p][0] = make_float2(0.f, 0.f); acc[p][1] = make_float2(0.f, 0.f); }

    for (int ci = 0; ci < nchunks32; ci++) {
        int kl = kstart + ci * 32;
        stage_A32(As, A, lda, kl);
        stage_W32(Ws, W, wld, n0, kl);
        __syncthreads();
        #pragma unroll
        for (int kk = 0; kk < 32; kk++) {
            float4 w4 = *(float4*)&Ws[kk][tx * 4];
            float2 wA = make_float2(w4.x, w4.y);
            float2 wB = make_float2(w4.z, w4.w);
            float4 a0 = *(float4*)&As[kk][ty * 8];
            float4 a1 = *(float4*)&As[kk][ty * 8 + 4];
            float av[8] = {a0.x, a0.y, a0.z, a0.w, a1.x, a1.y, a1.z, a1.w};
            #pragma unroll
            for (int p = 0; p < 8; p++) {
                float2 aa = make_float2(av[p], av[p]);
                fma2(acc[p][0], aa, wA);
                fma2(acc[p][1], aa, wB);
            }
        }
        __syncthreads();
    }
    #pragma unroll
    for (int p = 0; p < 8; p++) {
        int m = ty * 8 + p;
        float* cp = C + (size_t)m * ldc + n0 + tx * 4;
        atomicAdd(cp + 0, acc[p][0].x);
        atomicAdd(cp + 1, acc[p][0].y);
        atomicAdd(cp + 2, acc[p][1].x);
        atomicAdd(cp + 3, acc[p][1].y);
    }
}

// ------------------- logits body (K=512, bias + fused argmax), FFMA2 -------------------
__device__ __forceinline__ void dev_logits(
    float (*As)[68], float (*Ws)[132], int n0,
    const float* __restrict__ W, const float* __restrict__ bias,
    float* __restrict__ C, unsigned long long* __restrict__ amaxp)
{
    int tid = threadIdx.x;
    int tx = tid & 31, ty = tid >> 5;
    float2 acc[8][2];
    #pragma unroll
    for (int p = 0; p < 8; p++) { acc[p][0] = make_float2(0.f, 0.f); acc[p][1] = make_float2(0.f, 0.f); }

    const float* A = &g_h[1][0][0];
    for (int kl = 0; kl < HID; kl += 32) {
        stage_A32(As, A, HID, kl);
        stage_W32(Ws, W, HID, n0, kl);
        __syncthreads();
        #pragma unroll
        for (int kk = 0; kk < 32; kk++) {
            float4 w4 = *(float4*)&Ws[kk][tx * 4];
            float2 wA = make_float2(w4.x, w4.y);
            float2 wB = make_float2(w4.z, w4.w);
            float4 a0 = *(float4*)&As[kk][ty * 8];
            float4 a1 = *(float4*)&As[kk][ty * 8 + 4];
            float av[8] = {a0.x, a0.y, a0.z, a0.w, a1.x, a1.y, a1.z, a1.w};
            #pragma unroll
            for (int p = 0; p < 8; p++) {
                float2 aa = make_float2(av[p], av[p]);
                fma2(acc[p][0], aa, wA);
                fma2(acc[p][1], aa, wB);
            }
        }
        __syncthreads();
    }
    int n = n0 + tx * 4;
    float4 bv = *(const float4*)&bias[n];
    #pragma unroll
    for (int p = 0; p < 8; p++) {
        int m = ty * 8 + p;
        float4 v;
        v.x = acc[p][0].x + bv.x;
        v.y = acc[p][0].y + bv.y;
        v.z = acc[p][1].x + bv.z;
        v.w = acc[p][1].y + bv.w;
        *(float4*)(C + (size_t)m * VOC + n) = v;
        unsigned long long key = ((unsigned long long)fkey(v.x) << 32) | (unsigned)(~(n + 0));
        unsigned long long k2  = ((unsigned long long)fkey(v.y) << 32) | (unsigned)(~(n + 1));
        if (k2 > key) key = k2;
        k2 = ((unsigned long long)fkey(v.z) << 32) | (unsigned)(~(n + 2));
        if (k2 > key) key = k2;
        k2 = ((unsigned long long)fkey(v.w) << 32) | (unsigned)(~(n + 3));
        if (k2 > key) key = k2;
        #pragma unroll
        for (int off = 16; off > 0; off >>= 1) {
            unsigned long long o = __shfl_xor_sync(0xffffffffu, key, off);
            if (o > key) key = o;
        }
        if (tx == 0) atomicMax(&amaxp[m], key);
    }
}

// ------------------- attention body: inline r = h1@Wcomb + bcomb, scores/softmax/ctx
__device__ void dev_attn(float (*As)[68], float (*Ws)[132], int b,
                         const float* __restrict__ enc, const int* __restrict__ mask)
{
    float* sh1 = &As[0][0];          // 512 (As holds 32*68=2176 floats)
    float* sal = sh1 + 512;          // 128
    float* red = sal + SS;           // 4
    float* sr  = &Ws[0][0];          // 1024 (Ws holds 32*132=4224 floats)
    int tid = threadIdx.x, lane = tid & 31, warp = tid >> 5;

    *(float2*)&sh1[tid * 2] = *(const float2*)&g_h[1][b][tid * 2];
    __syncthreads();

    // r[d] = bcomb[d] + sum_j h1[j] * Wcomb[j][d]; 4 cols per thread
    {
        int d = tid * 4;
        float4 acc = *(const float4*)&g_bcomb[d];
        const float* wc = &g_wcomb[0][d];
        #pragma unroll 8
        for (int j = 0; j < HID; j++) {
            float hj = sh1[j];
            float4 w = *(const float4*)(wc + (size_t)j * DENC);
            acc.x += hj * w.x; acc.y += hj * w.y;
            acc.z += hj * w.z; acc.w += hj * w.w;
        }
        *(float4*)&sr[d] = acc;
    }
    __syncthreads();

    const float* eb = enc + (size_t)b * SS * DENC;
    #pragma unroll 1
    for (int i = 0; i < 16; i++) {
        int s = warp * 16 + i;
        const float* e = eb + (size_t)s * DENC;
        float acc = 0.f;
        #pragma unroll
        for (int d = lane * 4; d < DENC; d += 128) {
            float4 ev = *(const float4*)&e[d];
            float4 qv = *(const float4*)&sr[d];
            acc += ev.x * qv.x + ev.y * qv.y + ev.z * qv.z + ev.w * qv.w;
        }
        #pragma unroll
        for (int off = 16; off > 0; off >>= 1) acc += __shfl_down_sync(0xffffffffu, acc, off);
        if (lane == 0) sal[s] = mask[b * SS + s] ? MASKV : acc * (1.0f / 32.0f);
    }
    __syncthreads();
    float v = (tid < SS) ? sal[tid] : MASKV;
    float m = v;
    #pragma unroll
    for (int off = 16; off > 0; off >>= 1) m = fmaxf(m, __shfl_xor_sync(0xffffffffu, m, off));
    if (lane == 0 && warp < 4) red[warp] = m;
    __syncthreads();
    float bm = fmaxf(fmaxf(red[0], red[1]), fmaxf(red[2], red[3]));
    float e = (tid < SS) ? expf(v - bm) : 0.f;
    float sm_ = e;
    #pragma unroll
    for (int off = 16; off > 0; off >>= 1) sm_ += __shfl_xor_sync(0xffffffffu, sm_, off);
    __syncthreads();
    if (lane == 0 && warp < 4) red[warp] = sm_;
    __syncthreads();
    float tot = red[0] + red[1] + red[2] + red[3];
    if (tid < SS) sal[tid] = e / tot;
    __syncthreads();
    {
        int d = tid * 4;
        float4 acc = make_float4(0.f, 0.f, 0.f, 0.f);
        const float* e2 = eb + d;
        #pragma unroll 4
        for (int s = 0; s < SS; s++) {
            float a = sal[s];
            float4 ev = *(const float4*)(e2 + (size_t)s * DENC);
            acc.x += a * ev.x; acc.y += a * ev.y; acc.z += a * ev.z; acc.w += a * ev.w;
        }
        *(float4*)&g_ctx[b][d] = acc;
    }
}

// ------------------- union: attn || gates0-h || gates1-h || logits(t-1) -------------------
// mode=1: [0,BB)=attn, [BB,BB+2NG)=gates, rest=logits. mode=0: all blocks are logits.
__global__ void __launch_bounds__(256, 4) k_union(
    int mode, int hasLogits,
    const float* __restrict__ w_out, const float* __restrict__ b_out,
    float* __restrict__ Cl, unsigned long long* __restrict__ amaxW,
    const float* __restrict__ w_hh0, const float* __restrict__ w_hh1,
    float* __restrict__ g1p,
    const float* __restrict__ enc, const int* __restrict__ mask)
{
    __shared__ __align__(16) float As[32][68];
    __shared__ __align__(16) float Ws[32][132];
    int bx = blockIdx.x;
    if (mode) {
        if (bx < BB) {
            dev_attn(As, Ws, bx, enc, mask);
            return;
        }
        bx -= BB;
        if (bx < NG) {
            dev_gemm_body(As, Ws, &g_h[0][0][0], HID, w_hh0, HID,
                          (bx & 15) * 128, (bx >> 4) * 128, 4, &g_gates0[0][0], 4 * HID);
            return;
        }
        bx -= NG;
        if (bx < NG) {
            dev_gemm_body(As, Ws, &g_h[1][0][0], HID, w_hh1, HID,
                          (bx & 15) * 128, (bx >> 4) * 128, 4, g1p, 4 * HID);
            return;
        }
        bx -= NG;
    }
    if (hasLogits) dev_logits(As, Ws, bx * 128, w_out, b_out, Cl, amaxW);
}

// ------------------- gates0 x-part: [emb(pred) | ctx] @ w_ih0.T -------------------
__global__ void __launch_bounds__(256, 4) k_gx0(
    const float* __restrict__ emb_table, const float* __restrict__ w_ih0,
    const unsigned long long* __restrict__ amaxp)
{
    __shared__ __align__(16) float As[32][68];
    __shared__ __align__(16) float Ws[32][132];
    int tid = threadIdx.x;
    int tx = tid & 31, ty = tid >> 5;
    int n0 = blockIdx.x * 128;
    float2 acc[8][2];
    #pragma unroll
    for (int p = 0; p < 8; p++) { acc[p][0] = make_float2(0.f, 0.f); acc[p][1] = make_float2(0.f, 0.f); }

    int m = tid >> 2;
    int kq = (tid & 3) * 8;
    unsigned pred = ~(unsigned)(amaxp[m] & 0xFFFFFFFFull);

    #pragma unroll
    for (int chunk = 0; chunk < 4; chunk++) {
        int k0 = blockIdx.y * 128 + chunk * 32;
        const float* asrc = (k0 < EMB) ? emb_table + (size_t)pred * EMB + k0 + kq
                                       : &g_ctx[m][k0 - EMB + kq];
        {
            const float4* src = (const float4*)asrc;
            #pragma unroll
            for (int i = 0; i < 2; i++) {
                float4 v = src[i];
                As[kq + i * 4 + 0][m] = v.x; As[kq + i * 4 + 1][m] = v.y;
                As[kq + i * 4 + 2][m] = v.z; As[kq + i * 4 + 3][m] = v.w;
            }
        }
        stage_W32(Ws, w_ih0, EMB + DENC, n0, k0);
        __syncthreads();
        #pragma unroll
        for (int kk = 0; kk < 32; kk++) {
            float4 w4 = *(float4*)&Ws[kk][tx * 4];
            float2 wA = make_float2(w4.x, w4.y);
            float2 wB = make_float2(w4.z, w4.w);
            float4 a0 = *(float4*)&As[kk][ty * 8];
            float4 a1 = *(float4*)&As[kk][ty * 8 + 4];
            float av[8] = {a0.x, a0.y, a0.z, a0.w, a1.x, a1.y, a1.z, a1.w};
            #pragma unroll
            for (int p = 0; p < 8; p++) {
                float2 aa = make_float2(av[p], av[p]);
                fma2(acc[p][0], aa, wA);
                fma2(acc[p][1], aa, wB);
            }
        }
        __syncthreads();
    }
    #pragma unroll
    for (int p = 0; p < 8; p++) {
        int mm = ty * 8 + p;
        float* cp = &g_gates0[mm][n0 + tx * 4];
        atomicAdd(cp + 0, acc[p][0].x);
        atomicAdd(cp + 1, acc[p][0].y);
        atomicAdd(cp + 2, acc[p][1].x);
        atomicAdd(cp + 3, acc[p][1].y);
    }
}

// ------------------- gates1 x-part: h0_new @ w_ih1.T (8 k-splits) -------------------
__global__ void __launch_bounds__(256, 4) k_g1x(const float* __restrict__ w_ih1,
                                                float* __restrict__ g1p)
{
    __shared__ __align__(16) float As[32][68];
    __shared__ __align__(16) float Ws[32][132];
    dev_gemm_body(As, Ws, &g_h[0][0][0], HID, w_ih1, HID,
                  blockIdx.x * 128, blockIdx.y * 64, 2, g1p, 4 * HID);
}

// ------------------- one-time precomputes -------------------
__global__ void __launch_bounds__(256) k_wcomb(const float* __restrict__ wq,
                                               const float* __restrict__ wk) {
    __shared__ __align__(16) float Aq[64][68];
    __shared__ __align__(16) float Bk[64][68];
    int tid = threadIdx.x;
    int d0 = blockIdx.x * 64, j0 = blockIdx.y * 64;
    int tx = tid & 15, ty = tid >> 4;
    float2 acc[4][2];
    #pragma unroll
    for (int p = 0; p < 4; p++) { acc[p][0] = make_float2(0.f, 0.f); acc[p][1] = make_float2(0.f, 0.f); }
    int er = tid >> 4, c4 = (tid & 15) * 4;
    for (int e0 = 0; e0 < DENC; e0 += 64) {
        #pragma unroll
        for (int i = 0; i < 4; i++) {
            int e = e0 + er + i * 16;
            *(float4*)&Aq[er + i * 16][c4] = *(const float4*)&wq[(size_t)e * HID + j0 + c4];
            *(float4*)&Bk[er + i * 16][c4] = *(const float4*)&wk[(size_t)e * DENC + d0 + c4];
        }
        __syncthreads();
        #pragma unroll 8
        for (int kk = 0; kk < 64; kk++) {
            float4 a4 = *(float4*)&Aq[kk][ty * 4];
            float4 w4 = *(float4*)&Bk[kk][tx * 4];
            float2 wA = make_float2(w4.x, w4.y), wB = make_float2(w4.z, w4.w);
            float aa[4] = {a4.x, a4.y, a4.z, a4.w};
            #pragma unroll
            for (int p = 0; p < 4; p++) {
                float2 av = make_float2(aa[p], aa[p]);
                fma2(acc[p][0], av, wA);
                fma2(acc[p][1], av, wB);
            }
        }
        __syncthreads();
    }
    #pragma unroll
    for (int p = 0; p < 4; p++) {
        float4 v = make_float4(acc[p][0].x, acc[p][0].y, acc[p][1].x, acc[p][1].y);
        *(float4*)&g_wcomb[j0 + ty * 4 + p][d0 + tx * 4] = v;
    }
}

__global__ void k_bcomb(const float* __restrict__ bq, const float* __restrict__ wk) {
    int d = blockIdx.x * 256 + threadIdx.x;
    float acc = 0.f;
    #pragma unroll 8
    for (int e = 0; e < DENC; e++) acc += bq[e] * wk[(size_t)e * DENC + d];
    g_bcomb[d] = acc;
}

// ------------------- init -------------------
__global__ void __launch_bounds__(512) k_init(
    const float* __restrict__ b_ih0, const float* __restrict__ b_hh0,
    const float* __restrict__ b_ih1, const float* __restrict__ b_hh1)
{
    int idx = blockIdx.x * 512 + threadIdx.x;   // 32768
    float* h = &g_h[0][0][0];
    float* c = &g_c[0][0][0];
    #pragma unroll
    for (int i = idx; i < 2 * BB * HID; i += 32768) { h[i] = 0.f; c[i] = 0.f; }
    if (idx < BB) {
        g_amax2[1][idx] = (unsigned long long)(unsigned)(~1u);  // pred0 = START = 1
        g_amax2[0][idx] = 0ull;
    }
    int k4 = idx * 4;
    int kb = k4 & (4 * HID - 1);
    float4 a = *(const float4*)&b_ih0[kb];
    float4 c0 = *(const float4*)&b_hh0[kb];
    a.x += c0.x; a.y += c0.y; a.z += c0.z; a.w += c0.w;
    *(float4*)(&g_gates0[0][0] + k4) = a;
    float4 a1 = *(const float4*)&b_ih1[kb];
    float4 c1 = *(const float4*)&b_hh1[kb];
    a1.x += c1.x; a1.y += c1.y; a1.z += c1.z; a1.w += c1.w;
    *(float4*)(&g_gates1[0][0][0] + k4) = a1;
}

// ------------------- LSTM cells -------------------
__global__ void __launch_bounds__(512) k_cell0() {
    int idx = blockIdx.x * 512 + threadIdx.x;
    int b = idx >> 9, j = idx & (HID - 1);
    float i_ = g_gates0[b][j];
    float f_ = g_gates0[b][HID + j];
    float gg = g_gates0[b][2 * HID + j];
    float o_ = g_gates0[b][3 * HID + j];
    float c_new = sig_(f_) * g_c[0][b][j] + sig_(i_) * tanhf(gg);
    g_c[0][b][j] = c_new;
    g_h[0][b][j] = sig_(o_) * tanhf(c_new);
}

__global__ void __launch_bounds__(512) k_cell1(int p,
    const float* __restrict__ b_ih0, const float* __restrict__ b_hh0,
    const float* __restrict__ b_ih1, const float* __restrict__ b_hh1)
{
    int idx = blockIdx.x * 512 + threadIdx.x;
    int b = idx >> 9, j = idx & (HID - 1);
    float i_ = g_gates1[p][b][j];
    float f_ = g_gates1[p][b][HID + j];
    float gg = g_gates1[p][b][2 * HID + j];
    float o_ = g_gates1[p][b][3 * HID + j];
    float c_new = sig_(f_) * g_c[1][b][j] + sig_(i_) * tanhf(gg);
    g_c[1][b][j] = c_new;
    g_h[1][b][j] = sig_(o_) * tanhf(c_new);
    if (idx < BB) g_amax2[p][idx] = 0ull;
    // presets for step t+1
    int k4 = idx * 4;
    int kb = k4 & (4 * HID - 1);
    float4 a = *(const float4*)&b_ih0[kb];
    float4 c0 = *(const float4*)&b_hh0[kb];
    a.x += c0.x; a.y += c0.y; a.z += c0.z; a.w += c0.w;
    *(float4*)(&g_gates0[0][0] + k4) = a;
    float4 a1 = *(const float4*)&b_ih1[kb];
    float4 c1 = *(const float4*)&b_hh1[kb];
    a1.x += c1.x; a1.y += c1.y; a1.z += c1.z; a1.w += c1.w;
    *(float4*)(&g_gates1[1 - p][0][0] + k4) = a1;
}

// ------------------- final transpose (t,b,v) -> (b,v,t) -------------------
__global__ void __launch_bounds__(256) k_tr(float* __restrict__ out) {
    __shared__ float s[256][32];
    int b = blockIdx.y;
    int v0 = blockIdx.x * 256;
    int tid = threadIdx.x;
    #pragma unroll
    for (int t = 0; t < TSTEPS; t++)
        s[tid][t] = g_logits[((size_t)t * BB + b) * VOC + v0 + tid];
    __syncthreads();
    float* ob = out + ((size_t)b * VOC + v0) * TSTEPS;
    for (int i = tid; i < 256 * TSTEPS; i += 256)
        ob[i] = s[i / TSTEPS][i % TSTEPS];
}

// ------------------- launch -------------------
extern "C" void kernel_launch(void* const* d_in, const int* in_sizes, int n_in,
                              void* d_out, int out_size) {
    const float* enc   = (const float*)d_in[0];
    const int*   mask  = (const int*)d_in[1];
    const float* embt  = (const float*)d_in[2];
    const float* wq    = (const float*)d_in[3];
    const float* bq    = (const float*)d_in[4];
    const float* wk    = (const float*)d_in[5];
    const float* w_ih0 = (const float*)d_in[7];
    const float* w_hh0 = (const float*)d_in[8];
    const float* b_ih0 = (const float*)d_in[9];
    const float* b_hh0 = (const float*)d_in[10];
    const float* w_ih1 = (const float*)d_in[11];
    const float* w_hh1 = (const float*)d_in[12];
    const float* b_ih1 = (const float*)d_in[13];
    const float* b_hh1 = (const float*)d_in[14];
    const float* w_out = (const float*)d_in[15];
    const float* b_out = (const float*)d_in[16];
    float* out = (float*)d_out;

    float* glog = nullptr; float* gg1 = nullptr;
    unsigned long long* gam = nullptr;
    cudaGetSymbolAddress((void**)&glog, g_logits);
    cudaGetSymbolAddress((void**)&gg1, g_gates1);
    cudaGetSymbolAddress((void**)&gam, g_amax2);

    k_wcomb<<<dim3(16, 8), 256>>>(wq, wk);
    k_bcomb<<<4, 256>>>(bq, wk);
    k_init<<<64, 512>>>(b_ih0, b_hh0, b_ih1, b_hh1);

    for (int t = 0; t < TSTEPS; t++) {
        int p = t & 1;
        int pm = (t > 0) ? ((t - 1) & 1) : 0;
        k_union<<<BB + 2 * NG + NLOG, 256>>>(
            1, t > 0, w_out, b_out,
            glog + (size_t)(t > 0 ? t - 1 : 0) * BB * VOC,
            gam + (size_t)pm * BB,
            w_hh0, w_hh1,
            gg1 + (size_t)p * BB * 4 * HID,
            enc, mask);
        k_gx0<<<dim3(16, 12), 256>>>(embt, w_ih0, gam + (size_t)(1 - p) * BB);
        k_cell0<<<64, 512>>>();
        k_g1x<<<dim3(16, 8), 256>>>(w_ih1, gg1 + (size_t)p * BB * 4 * HID);
        k_cell1<<<64, 512>>>(p, b_ih0, b_hh0, b_ih1, b_hh1);
    }
    // final logits (t = TSTEPS-1): parity of 30 is 0
    k_union<<<NLOG, 256>>>(0, 1, w_out, b_out,
                           glog + (size_t)(TSTEPS - 1) * BB * VOC,
                           gam + 0, w_hh0, w_hh1, gg1, enc, mask);
    k_tr<<<dim3(VOC / 256, BB), 256>>>(out);
}

// round 14
// speedup vs baseline: 1.1870x; 1.0208x over previous
#include <cuda_runtime.h>
#include <math.h>

#define BB    64
#define SS    128
#define DENC  1024
#define HID   512
#define EMB   512
#define VOC   32000
#define TSTEPS 31
#define MASKV -10000000000.0f
#define NLOG  (VOC / 128)     // 250 logits blocks
#define NG    64              // gates-h blocks each (16 n-tiles x 4 k-splits)

// ------------------- static scratch -------------------
__device__ __align__(256) float g_h[2][BB][HID];
__device__ __align__(256) float g_c[2][BB][HID];
__device__ __align__(256) float g_ctx[BB][DENC];
__device__ __align__(256) float g_gates0[BB][4 * HID];
__device__ __align__(256) float g_gates1[2][BB][4 * HID];       // double-buffered
__device__ __align__(256) unsigned long long g_amax2[2][BB];    // double-buffered
__device__ __align__(256) float g_wcomb[HID][DENC];             // Wcomb[j][d]
__device__ __align__(256) float g_bcomb[DENC];                  // bq @ wk
__device__ __align__(256) float g_logits[(size_t)TSTEPS * BB * VOC];   // (t,b,v)

// ------------------- helpers -------------------
__device__ __forceinline__ void fma2(float2& c, float2 a, float2 b) {
    union { float2 f; unsigned long long u; } uc, ua, ub;
    uc.f = c; ua.f = a; ub.f = b;
    asm("fma.rn.f32x2 %0, %1, %2, %0;" : "+l"(uc.u) : "l"(ua.u), "l"(ub.u));
    c = uc.f;
}
__device__ __forceinline__ unsigned fkey(float f) {
    unsigned u = __float_as_uint(f);
    return (u & 0x80000000u) ? ~u : (u | 0x80000000u);
}
__device__ __forceinline__ float sig_(float x) { return 1.0f / (1.0f + expf(-x)); }

// ------------------- staging helpers (32-k chunks, 256 threads) -------------------
__device__ __forceinline__ void stage_A32(float (*As)[68], const float* A, int lda, int kl) {
    int tid = threadIdx.x;
    int m = tid >> 2;
    int kq = (tid & 3) * 8;
    const float4* src = (const float4*)(A + (size_t)m * lda + kl + kq);
    #pragma unroll
    for (int i = 0; i < 2; i++) {
        float4 v = src[i];
        As[kq + i * 4 + 0][m] = v.x; As[kq + i * 4 + 1][m] = v.y;
        As[kq + i * 4 + 2][m] = v.z; As[kq + i * 4 + 3][m] = v.w;
    }
}
__device__ __forceinline__ void stage_W32(float (*Ws)[132], const float* W, int wld,
                                          int n0, int kl) {
    int tid = threadIdx.x;
    int nn = tid >> 1;
    int kq2 = (tid & 1) * 16;
    const float4* src = (const float4*)(W + (size_t)(n0 + nn) * wld + kl + kq2);
    #pragma unroll
    for (int i = 0; i < 4; i++) {
        float4 v = src[i];
        Ws[kq2 + i * 4 + 0][nn] = v.x; Ws[kq2 + i * 4 + 1][nn] = v.y;
        Ws[kq2 + i * 4 + 2][nn] = v.z; Ws[kq2 + i * 4 + 3][nn] = v.w;
    }
}

// ------------------- generic 64xN GEMM body (W n-major), 256 threads -------------------
__device__ __forceinline__ void dev_gemm_body(
    float (*As)[68], float (*Ws)[132],
    const float* __restrict__ A, int lda,
    const float* __restrict__ W, int wld,
    int n0, int kstart, int nchunks32,
    float* __restrict__ C, int ldc)
{
    int tid = threadIdx.x;
    int tx = tid & 31, ty = tid >> 5;
    float2 acc[8][2];
    #pragma unroll
    for (int p = 0; p < 8; p++) { acc[p][0] = make_float2(0.f, 0.f); acc[p][1] = make_float2(0.f, 0.f); }

    for (int ci = 0; ci < nchunks32; ci++) {
        int kl = kstart + ci * 32;
        stage_A32(As, A, lda, kl);
        stage_W32(Ws, W, wld, n0, kl);
        __syncthreads();
        #pragma unroll
        for (int kk = 0; kk < 32; kk++) {
            float4 w4 = *(float4*)&Ws[kk][tx * 4];
            float2 wA = make_float2(w4.x, w4.y);
            float2 wB = make_float2(w4.z, w4.w);
            float4 a0 = *(float4*)&As[kk][ty * 8];
            float4 a1 = *(float4*)&As[kk][ty * 8 + 4];
            float av[8] = {a0.x, a0.y, a0.z, a0.w, a1.x, a1.y, a1.z, a1.w};
            #pragma unroll
            for (int p = 0; p < 8; p++) {
                float2 aa = make_float2(av[p], av[p]);
                fma2(acc[p][0], aa, wA);
                fma2(acc[p][1], aa, wB);
            }
        }
        __syncthreads();
    }
    #pragma unroll
    for (int p = 0; p < 8; p++) {
        int m = ty * 8 + p;
        float* cp = C + (size_t)m * ldc + n0 + tx * 4;
        atomicAdd(cp + 0, acc[p][0].x);
        atomicAdd(cp + 1, acc[p][0].y);
        atomicAdd(cp + 2, acc[p][1].x);
        atomicAdd(cp + 3, acc[p][1].y);
    }
}

// ------------------- logits body (K=512, bias + fused argmax), FFMA2 -------------------
__device__ __forceinline__ void dev_logits(
    float (*As)[68], float (*Ws)[132], int n0,
    const float* __restrict__ W, const float* __restrict__ bias,
    float* __restrict__ C, unsigned long long* __restrict__ amaxp)
{
    int tid = threadIdx.x;
    int tx = tid & 31, ty = tid >> 5;
    float2 acc[8][2];
    #pragma unroll
    for (int p = 0; p < 8; p++) { acc[p][0] = make_float2(0.f, 0.f); acc[p][1] = make_float2(0.f, 0.f); }

    const float* A = &g_h[1][0][0];
    for (int kl = 0; kl < HID; kl += 32) {
        stage_A32(As, A, HID, kl);
        stage_W32(Ws, W, HID, n0, kl);
        __syncthreads();
        #pragma unroll
        for (int kk = 0; kk < 32; kk++) {
            float4 w4 = *(float4*)&Ws[kk][tx * 4];
            float2 wA = make_float2(w4.x, w4.y);
            float2 wB = make_float2(w4.z, w4.w);
            float4 a0 = *(float4*)&As[kk][ty * 8];
            float4 a1 = *(float4*)&As[kk][ty * 8 + 4];
            float av[8] = {a0.x, a0.y, a0.z, a0.w, a1.x, a1.y, a1.z, a1.w};
            #pragma unroll
            for (int p = 0; p < 8; p++) {
                float2 aa = make_float2(av[p], av[p]);
                fma2(acc[p][0], aa, wA);
                fma2(acc[p][1], aa, wB);
            }
        }
        __syncthreads();
    }
    int n = n0 + tx * 4;
    float4 bv = *(const float4*)&bias[n];
    #pragma unroll
    for (int p = 0; p < 8; p++) {
        int m = ty * 8 + p;
        float4 v;
        v.x = acc[p][0].x + bv.x;
        v.y = acc[p][0].y + bv.y;
        v.z = acc[p][1].x + bv.z;
        v.w = acc[p][1].y + bv.w;
        *(float4*)(C + (size_t)m * VOC + n) = v;
        unsigned long long key = ((unsigned long long)fkey(v.x) << 32) | (unsigned)(~(n + 0));
        unsigned long long k2  = ((unsigned long long)fkey(v.y) << 32) | (unsigned)(~(n + 1));
        if (k2 > key) key = k2;
        k2 = ((unsigned long long)fkey(v.z) << 32) | (unsigned)(~(n + 2));
        if (k2 > key) key = k2;
        k2 = ((unsigned long long)fkey(v.w) << 32) | (unsigned)(~(n + 3));
        if (k2 > key) key = k2;
        #pragma unroll
        for (int off = 16; off > 0; off >>= 1) {
            unsigned long long o = __shfl_xor_sync(0xffffffffu, key, off);
            if (o > key) key = o;
        }
        if (tx == 0) atomicMax(&amaxp[m], key);
    }
}

// ------------------- attention body: inline r = h1@Wcomb + bcomb, scores/softmax/ctx
__device__ void dev_attn(float (*As)[68], float (*Ws)[132], int b,
                         const float* __restrict__ enc, const int* __restrict__ mask)
{
    float* sh1 = &As[0][0];          // 512
    float* sal = sh1 + 512;          // 128
    float* red = sal + SS;           // 4
    float* sr  = &Ws[0][0];          // 1024
    int tid = threadIdx.x, lane = tid & 31, warp = tid >> 5;

    *(float2*)&sh1[tid * 2] = *(const float2*)&g_h[1][b][tid * 2];
    __syncthreads();

    // r[d] = bcomb[d] + sum_j h1[j] * Wcomb[j][d]; 4 cols per thread, MLP 16
    {
        int d = tid * 4;
        float4 acc = *(const float4*)&g_bcomb[d];
        const float* wc = &g_wcomb[0][d];
        #pragma unroll 16
        for (int j = 0; j < HID; j++) {
            float hj = sh1[j];
            float4 w = *(const float4*)(wc + (size_t)j * DENC);
            acc.x += hj * w.x; acc.y += hj * w.y;
            acc.z += hj * w.z; acc.w += hj * w.w;
        }
        *(float4*)&sr[d] = acc;
    }
    __syncthreads();

    const float* eb = enc + (size_t)b * SS * DENC;
    #pragma unroll 1
    for (int i = 0; i < 16; i++) {
        int s = warp * 16 + i;
        const float* e = eb + (size_t)s * DENC;
        float acc = 0.f;
        #pragma unroll
        for (int d = lane * 4; d < DENC; d += 128) {
            float4 ev = *(const float4*)&e[d];
            float4 qv = *(const float4*)&sr[d];
            acc += ev.x * qv.x + ev.y * qv.y + ev.z * qv.z + ev.w * qv.w;
        }
        #pragma unroll
        for (int off = 16; off > 0; off >>= 1) acc += __shfl_down_sync(0xffffffffu, acc, off);
        if (lane == 0) sal[s] = mask[b * SS + s] ? MASKV : acc * (1.0f / 32.0f);
    }
    __syncthreads();
    float v = (tid < SS) ? sal[tid] : MASKV;
    float m = v;
    #pragma unroll
    for (int off = 16; off > 0; off >>= 1) m = fmaxf(m, __shfl_xor_sync(0xffffffffu, m, off));
    if (lane == 0 && warp < 4) red[warp] = m;
    __syncthreads();
    float bm = fmaxf(fmaxf(red[0], red[1]), fmaxf(red[2], red[3]));
    float e = (tid < SS) ? expf(v - bm) : 0.f;
    float sm_ = e;
    #pragma unroll
    for (int off = 16; off > 0; off >>= 1) sm_ += __shfl_xor_sync(0xffffffffu, sm_, off);
    __syncthreads();
    if (lane == 0 && warp < 4) red[warp] = sm_;
    __syncthreads();
    float tot = red[0] + red[1] + red[2] + red[3];
    if (tid < SS) sal[tid] = e / tot;
    __syncthreads();
    {
        int d = tid * 4;
        float4 acc = make_float4(0.f, 0.f, 0.f, 0.f);
        const float* e2 = eb + d;
        #pragma unroll 8
        for (int s = 0; s < SS; s++) {
            float a = sal[s];
            float4 ev = *(const float4*)(e2 + (size_t)s * DENC);
            acc.x += a * ev.x; acc.y += a * ev.y; acc.z += a * ev.z; acc.w += a * ev.w;
        }
        *(float4*)&g_ctx[b][d] = acc;
    }
}

// ------------------- union: attn || gates0-h || gates1-h || logits(t-1) -------------------
__global__ void __launch_bounds__(256, 4) k_union(
    int mode, int hasLogits,
    const float* __restrict__ w_out, const float* __restrict__ b_out,
    float* __restrict__ Cl, unsigned long long* __restrict__ amaxW,
    const float* __restrict__ w_hh0, const float* __restrict__ w_hh1,
    float* __restrict__ g1p,
    const float* __restrict__ enc, const int* __restrict__ mask)
{
    __shared__ __align__(16) float As[32][68];
    __shared__ __align__(16) float Ws[32][132];
    int bx = blockIdx.x;
    if (mode) {
        if (bx < BB) {
            dev_attn(As, Ws, bx, enc, mask);
            return;
        }
        bx -= BB;
        if (bx < NG) {
            dev_gemm_body(As, Ws, &g_h[0][0][0], HID, w_hh0, HID,
                          (bx & 15) * 128, (bx >> 4) * 128, 4, &g_gates0[0][0], 4 * HID);
            return;
        }
        bx -= NG;
        if (bx < NG) {
            dev_gemm_body(As, Ws, &g_h[1][0][0], HID, w_hh1, HID,
                          (bx & 15) * 128, (bx >> 4) * 128, 4, g1p, 4 * HID);
            return;
        }
        bx -= NG;
    }
    if (hasLogits) dev_logits(As, Ws, bx * 128, w_out, b_out, Cl, amaxW);
}

// ------------------- gates0 x-part: [emb(pred) | ctx] @ w_ih0.T (24 k-splits) -------------------
__global__ void __launch_bounds__(256, 4) k_gx0(
    const float* __restrict__ emb_table, const float* __restrict__ w_ih0,
    const unsigned long long* __restrict__ amaxp)
{
    __shared__ __align__(16) float As[32][68];
    __shared__ __align__(16) float Ws[32][132];
    int tid = threadIdx.x;
    int tx = tid & 31, ty = tid >> 5;
    int n0 = blockIdx.x * 128;
    float2 acc[8][2];
    #pragma unroll
    for (int p = 0; p < 8; p++) { acc[p][0] = make_float2(0.f, 0.f); acc[p][1] = make_float2(0.f, 0.f); }

    int m = tid >> 2;
    int kq = (tid & 3) * 8;
    unsigned pred = ~(unsigned)(amaxp[m] & 0xFFFFFFFFull);

    #pragma unroll
    for (int chunk = 0; chunk < 2; chunk++) {
        int k0 = blockIdx.y * 64 + chunk * 32;
        const float* asrc = (k0 < EMB) ? emb_table + (size_t)pred * EMB + k0 + kq
                                       : &g_ctx[m][k0 - EMB + kq];
        {
            const float4* src = (const float4*)asrc;
            #pragma unroll
            for (int i = 0; i < 2; i++) {
                float4 v = src[i];
                As[kq + i * 4 + 0][m] = v.x; As[kq + i * 4 + 1][m] = v.y;
                As[kq + i * 4 + 2][m] = v.z; As[kq + i * 4 + 3][m] = v.w;
            }
        }
        stage_W32(Ws, w_ih0, EMB + DENC, n0, k0);
        __syncthreads();
        #pragma unroll
        for (int kk = 0; kk < 32; kk++) {
            float4 w4 = *(float4*)&Ws[kk][tx * 4];
            float2 wA = make_float2(w4.x, w4.y);
            float2 wB = make_float2(w4.z, w4.w);
            float4 a0 = *(float4*)&As[kk][ty * 8];
            float4 a1 = *(float4*)&As[kk][ty * 8 + 4];
            float av[8] = {a0.x, a0.y, a0.z, a0.w, a1.x, a1.y, a1.z, a1.w};
            #pragma unroll
            for (int p = 0; p < 8; p++) {
                float2 aa = make_float2(av[p], av[p]);
                fma2(acc[p][0], aa, wA);
                fma2(acc[p][1], aa, wB);
            }
        }
        __syncthreads();
    }
    #pragma unroll
    for (int p = 0; p < 8; p++) {
        int mm = ty * 8 + p;
        float* cp = &g_gates0[mm][n0 + tx * 4];
        atomicAdd(cp + 0, acc[p][0].x);
        atomicAdd(cp + 1, acc[p][0].y);
        atomicAdd(cp + 2, acc[p][1].x);
        atomicAdd(cp + 3, acc[p][1].y);
    }
}

// ------------------- gates1 x-part: h0_new @ w_ih1.T (16 k-splits) -------------------
__global__ void __launch_bounds__(256, 4) k_g1x(const float* __restrict__ w_ih1,
                                                float* __restrict__ g1p)
{
    __shared__ __align__(16) float As[32][68];
    __shared__ __align__(16) float Ws[32][132];
    dev_gemm_body(As, Ws, &g_h[0][0][0], HID, w_ih1, HID,
                  blockIdx.x * 128, blockIdx.y * 32, 1, g1p, 4 * HID);
}

// ------------------- one-time precomputes -------------------
__global__ void __launch_bounds__(256) k_wcomb(const float* __restrict__ wq,
                                               const float* __restrict__ wk) {
    __shared__ __align__(16) float Aq[64][68];
    __shared__ __align__(16) float Bk[64][68];
    int tid = threadIdx.x;
    int d0 = blockIdx.x * 64, j0 = blockIdx.y * 64;
    int tx = tid & 15, ty = tid >> 4;
    float2 acc[4][2];
    #pragma unroll
    for (int p = 0; p < 4; p++) { acc[p][0] = make_float2(0.f, 0.f); acc[p][1] = make_float2(0.f, 0.f); }
    int er = tid >> 4, c4 = (tid & 15) * 4;
    for (int e0 = 0; e0 < DENC; e0 += 64) {
        #pragma unroll
        for (int i = 0; i < 4; i++) {
            int e = e0 + er + i * 16;
            *(float4*)&Aq[er + i * 16][c4] = *(const float4*)&wq[(size_t)e * HID + j0 + c4];
            *(float4*)&Bk[er + i * 16][c4] = *(const float4*)&wk[(size_t)e * DENC + d0 + c4];
        }
        __syncthreads();
        #pragma unroll 8
        for (int kk = 0; kk < 64; kk++) {
            float4 a4 = *(float4*)&Aq[kk][ty * 4];
            float4 w4 = *(float4*)&Bk[kk][tx * 4];
            float2 wA = make_float2(w4.x, w4.y), wB = make_float2(w4.z, w4.w);
            float aa[4] = {a4.x, a4.y, a4.z, a4.w};
            #pragma unroll
            for (int p = 0; p < 4; p++) {
                float2 av = make_float2(aa[p], aa[p]);
                fma2(acc[p][0], av, wA);
                fma2(acc[p][1], av, wB);
            }
        }
        __syncthreads();
    }
    #pragma unroll
    for (int p = 0; p < 4; p++) {
        float4 v = make_float4(acc[p][0].x, acc[p][0].y, acc[p][1].x, acc[p][1].y);
        *(float4*)&g_wcomb[j0 + ty * 4 + p][d0 + tx * 4] = v;
    }
}

__global__ void k_bcomb(const float* __restrict__ bq, const float* __restrict__ wk) {
    int d = blockIdx.x * 256 + threadIdx.x;
    float acc = 0.f;
    #pragma unroll 8
    for (int e = 0; e < DENC; e++) acc += bq[e] * wk[(size_t)e * DENC + d];
    g_bcomb[d] = acc;
}

// ------------------- init -------------------
__global__ void __launch_bounds__(512) k_init(
    const float* __restrict__ b_ih0, const float* __restrict__ b_hh0,
    const float* __restrict__ b_ih1, const float* __restrict__ b_hh1)
{
    int idx = blockIdx.x * 512 + threadIdx.x;   // 32768
    float* h = &g_h[0][0][0];
    float* c = &g_c[0][0][0];
    #pragma unroll
    for (int i = idx; i < 2 * BB * HID; i += 32768) { h[i] = 0.f; c[i] = 0.f; }
    if (idx < BB) {
        g_amax2[1][idx] = (unsigned long long)(unsigned)(~1u);  // pred0 = START = 1
        g_amax2[0][idx] = 0ull;
    }
    int k4 = idx * 4;
    int kb = k4 & (4 * HID - 1);
    float4 a = *(const float4*)&b_ih0[kb];
    float4 c0 = *(const float4*)&b_hh0[kb];
    a.x += c0.x; a.y += c0.y; a.z += c0.z; a.w += c0.w;
    *(float4*)(&g_gates0[0][0] + k4) = a;
    float4 a1 = *(const float4*)&b_ih1[kb];
    float4 c1 = *(const float4*)&b_hh1[kb];
    a1.x += c1.x; a1.y += c1.y; a1.z += c1.z; a1.w += c1.w;
    *(float4*)(&g_gates1[0][0][0] + k4) = a1;
}

// ------------------- LSTM cells -------------------
__global__ void __launch_bounds__(512) k_cell0() {
    int idx = blockIdx.x * 512 + threadIdx.x;
    int b = idx >> 9, j = idx & (HID - 1);
    float i_ = g_gates0[b][j];
    float f_ = g_gates0[b][HID + j];
    float gg = g_gates0[b][2 * HID + j];
    float o_ = g_gates0[b][3 * HID + j];
    float c_new = sig_(f_) * g_c[0][b][j] + sig_(i_) * tanhf(gg);
    g_c[0][b][j] = c_new;
    g_h[0][b][j] = sig_(o_) * tanhf(c_new);
}

__global__ void __launch_bounds__(512) k_cell1(int p,
    const float* __restrict__ b_ih0, const float* __restrict__ b_hh0,
    const float* __restrict__ b_ih1, const float* __restrict__ b_hh1)
{
    int idx = blockIdx.x * 512 + threadIdx.x;
    int b = idx >> 9, j = idx & (HID - 1);
    float i_ = g_gates1[p][b][j];
    float f_ = g_gates1[p][b][HID + j];
    float gg = g_gates1[p][b][2 * HID + j];
    float o_ = g_gates1[p][b][3 * HID + j];
    float c_new = sig_(f_) * g_c[1][b][j] + sig_(i_) * tanhf(gg);
    g_c[1][b][j] = c_new;
    g_h[1][b][j] = sig_(o_) * tanhf(c_new);
    if (idx < BB) g_amax2[p][idx] = 0ull;
    // presets for step t+1
    int k4 = idx * 4;
    int kb = k4 & (4 * HID - 1);
    float4 a = *(const float4*)&b_ih0[kb];
    float4 c0 = *(const float4*)&b_hh0[kb];
    a.x += c0.x; a.y += c0.y; a.z += c0.z; a.w += c0.w;
    *(float4*)(&g_gates0[0][0] + k4) = a;
    float4 a1 = *(const float4*)&b_ih1[kb];
    float4 c1 = *(const float4*)&b_hh1[kb];
    a1.x += c1.x; a1.y += c1.y; a1.z += c1.z; a1.w += c1.w;
    *(float4*)(&g_gates1[1 - p][0][0] + k4) = a1;
}

// ------------------- final transpose (t,b,v) -> (b,v,t) -------------------
__global__ void __launch_bounds__(256) k_tr(float* __restrict__ out) {
    __shared__ float s[256][32];
    int b = blockIdx.y;
    int v0 = blockIdx.x * 256;
    int tid = threadIdx.x;
    #pragma unroll
    for (int t = 0; t < TSTEPS; t++)
        s[tid][t] = g_logits[((size_t)t * BB + b) * VOC + v0 + tid];
    __syncthreads();
    float* ob = out + ((size_t)b * VOC + v0) * TSTEPS;
    for (int i = tid; i < 256 * TSTEPS; i += 256)
        ob[i] = s[i / TSTEPS][i % TSTEPS];
}

// ------------------- launch -------------------
extern "C" void kernel_launch(void* const* d_in, const int* in_sizes, int n_in,
                              void* d_out, int out_size) {
    const float* enc   = (const float*)d_in[0];
    const int*   mask  = (const int*)d_in[1];
    const float* embt  = (const float*)d_in[2];
    const float* wq    = (const float*)d_in[3];
    const float* bq    = (const float*)d_in[4];
    const float* wk    = (const float*)d_in[5];
    const float* w_ih0 = (const float*)d_in[7];
    const float* w_hh0 = (const float*)d_in[8];
    const float* b_ih0 = (const float*)d_in[9];
    const float* b_hh0 = (const float*)d_in[10];
    const float* w_ih1 = (const float*)d_in[11];
    const float* w_hh1 = (const float*)d_in[12];
    const float* b_ih1 = (const float*)d_in[13];
    const float* b_hh1 = (const float*)d_in[14];
    const float* w_out = (const float*)d_in[15];
    const float* b_out = (const float*)d_in[16];
    float* out = (float*)d_out;

    float* glog = nullptr; float* gg1 = nullptr;
    unsigned long long* gam = nullptr;
    cudaGetSymbolAddress((void**)&glog, g_logits);
    cudaGetSymbolAddress((void**)&gg1, g_gates1);
    cudaGetSymbolAddress((void**)&gam, g_amax2);

    k_wcomb<<<dim3(16, 8), 256>>>(wq, wk);
    k_bcomb<<<4, 256>>>(bq, wk);
    k_init<<<64, 512>>>(b_ih0, b_hh0, b_ih1, b_hh1);

    for (int t = 0; t < TSTEPS; t++) {
        int p = t & 1;
        int pm = (t > 0) ? ((t - 1) & 1) : 0;
        k_union<<<BB + 2 * NG + NLOG, 256>>>(
            1, t > 0, w_out, b_out,
            glog + (size_t)(t > 0 ? t - 1 : 0) * BB * VOC,
            gam + (size_t)pm * BB,
            w_hh0, w_hh1,
            gg1 + (size_t)p * BB * 4 * HID,
            enc, mask);
        k_gx0<<<dim3(16, 24), 256>>>(embt, w_ih0, gam + (size_t)(1 - p) * BB);
        k_cell0<<<64, 512>>>();
        k_g1x<<<dim3(16, 16), 256>>>(w_ih1, gg1 + (size_t)p * BB * 4 * HID);
        k_cell1<<<64, 512>>>(p, b_ih0, b_hh0, b_ih1, b_hh1);
    }
    // final logits (t = TSTEPS-1): parity of 30 is 0
    k_union<<<NLOG, 256>>>(0, 1, w_out, b_out,
                           glog + (size_t)(TSTEPS - 1) * BB * VOC,
                           gam + 0, w_hh0, w_hh1, gg1, enc, mask);
    k_tr<<<dim3(VOC / 256, BB), 256>>>(out);
}